// round 1
// baseline (speedup 1.0000x reference)
#include <cuda_runtime.h>

// ---------------- problem constants ----------------
#define CB   64            // batch
#define CT   512           // time steps
#define CD   1024          // input dim
#define CN   1024          // ACT_DIM == UOUT
#define S_   16            // scan block size
#define NBLK 32            // CT / S_
#define MROWS (CB * CT)    // 32768
#define MST   (CB * NBLK)  // 2048 (batched-scan rows)

// ---------------- scratch (__device__ globals; no runtime alloc) ----------------
__device__ float g_xp[(size_t)MROWS * CN];   // Xp, then overwritten in-place with a_t (pass 3)
__device__ float g_s1[(size_t)MST * CN];     // scan state ping
__device__ float g_s2[(size_t)MST * CN];     // scan state pong
__device__ float g_bd[(size_t)NBLK * CB * CN]; // boundary states b_k
__device__ float g_pA[(size_t)CN * CN];      // matrix-power ping
__device__ float g_pB[(size_t)CN * CN];      // matrix-power pong (holds Waa^16)
__device__ float g_part[(size_t)8 * CB * CN]; // split-K partials for boundary steps

// =====================================================================
// Generic fp32 SGEMM: C[M,N] = A[M,K] @ op(W) + bias
//   TRANSB=1: op(W)=W^T with W stored [N,K]  (x @ W^T style)
//   TRANSB=0: op(W)=W   with W stored [K,N]  (matrix squaring)
// Requires M%128==0, N%128==0, K%16==0 (all call sites satisfy this).
// 128x128 tile, BK=16, 256 threads, 8x8 per-thread microtile.
// =====================================================================
template <int TRANSB>
__global__ __launch_bounds__(256) void sgemm_k(
    const float* __restrict__ A, const float* __restrict__ W,
    const float* __restrict__ bias, float* __restrict__ C,
    int M, int N, int K)
{
    __shared__ float As[16][132];
    __shared__ float Bs[16][132];
    const int tid  = threadIdx.x;
    const int tx   = tid & 15, ty = tid >> 4;
    const int row0 = blockIdx.y * 128, col0 = blockIdx.x * 128;
    const int lr   = tid >> 2;          // 0..63
    const int lc   = (tid & 3) << 2;    // 0,4,8,12

    float acc[8][8];
#pragma unroll
    for (int i = 0; i < 8; i++)
#pragma unroll
        for (int j = 0; j < 8; j++) acc[i][j] = 0.f;

    for (int k0 = 0; k0 < K; k0 += 16) {
#pragma unroll
        for (int rr = 0; rr < 128; rr += 64) {
            float4 v = *(const float4*)&A[(size_t)(row0 + lr + rr) * K + k0 + lc];
            As[lc + 0][lr + rr] = v.x; As[lc + 1][lr + rr] = v.y;
            As[lc + 2][lr + rr] = v.z; As[lc + 3][lr + rr] = v.w;
        }
        if (TRANSB) {
#pragma unroll
            for (int rr = 0; rr < 128; rr += 64) {
                float4 v = *(const float4*)&W[(size_t)(col0 + lr + rr) * K + k0 + lc];
                Bs[lc + 0][lr + rr] = v.x; Bs[lc + 1][lr + rr] = v.y;
                Bs[lc + 2][lr + rr] = v.z; Bs[lc + 3][lr + rr] = v.w;
            }
        } else {
            const int kr = tid >> 5;         // 0..7
            const int nc = (tid & 31) << 2;  // 0..124
#pragma unroll
            for (int rr = 0; rr < 16; rr += 8) {
                float4 v = *(const float4*)&W[(size_t)(k0 + kr + rr) * N + col0 + nc];
                *(float4*)&Bs[kr + rr][nc] = v;
            }
        }
        __syncthreads();
#pragma unroll
        for (int kk = 0; kk < 16; kk++) {
            float a[8], b[8];
            *(float4*)&a[0] = *(const float4*)&As[kk][ty * 8];
            *(float4*)&a[4] = *(const float4*)&As[kk][ty * 8 + 4];
            *(float4*)&b[0] = *(const float4*)&Bs[kk][tx * 8];
            *(float4*)&b[4] = *(const float4*)&Bs[kk][tx * 8 + 4];
#pragma unroll
            for (int i = 0; i < 8; i++)
#pragma unroll
                for (int j = 0; j < 8; j++) acc[i][j] += a[i] * b[j];
        }
        __syncthreads();
    }

#pragma unroll
    for (int i = 0; i < 8; i++) {
        const size_t m = (size_t)row0 + ty * 8 + i;
#pragma unroll
        for (int j = 0; j < 8; j += 4) {
            const int n = col0 + tx * 8 + j;
            float4 v = make_float4(acc[i][j], acc[i][j + 1], acc[i][j + 2], acc[i][j + 3]);
            if (bias) {
                v.x += bias[n];     v.y += bias[n + 1];
                v.z += bias[n + 2]; v.w += bias[n + 3];
            }
            *(float4*)&C[m * N + n] = v;
        }
    }
}

// =====================================================================
// Batched scan step: Sout[r,:] = Sin[r,:] @ Waa^T + Xp[t(r),:]
//   r = bb*32 + blk (bb=batch 0..63, blk=block 0..31), t = blk*16 + jstep
//   STOREXP=1 additionally writes the result back into Xp (pass 3 stores a_t)
// M=2048, N=K=1024 fixed. Same tiling as sgemm_k.
// =====================================================================
template <int STOREXP>
__global__ __launch_bounds__(256) void step_k(
    const float* __restrict__ Sin, const float* __restrict__ Wq,
    float* __restrict__ Xp, int jstep, float* __restrict__ Sout)
{
    __shared__ float As[16][132];
    __shared__ float Bs[16][132];
    const int tid  = threadIdx.x;
    const int tx   = tid & 15, ty = tid >> 4;
    const int row0 = blockIdx.y * 128, col0 = blockIdx.x * 128;
    const int lr   = tid >> 2;
    const int lc   = (tid & 3) << 2;

    float acc[8][8];
#pragma unroll
    for (int i = 0; i < 8; i++)
#pragma unroll
        for (int j = 0; j < 8; j++) acc[i][j] = 0.f;

    for (int k0 = 0; k0 < CN; k0 += 16) {
#pragma unroll
        for (int rr = 0; rr < 128; rr += 64) {
            float4 v = *(const float4*)&Sin[(size_t)(row0 + lr + rr) * CN + k0 + lc];
            As[lc + 0][lr + rr] = v.x; As[lc + 1][lr + rr] = v.y;
            As[lc + 2][lr + rr] = v.z; As[lc + 3][lr + rr] = v.w;
        }
#pragma unroll
        for (int rr = 0; rr < 128; rr += 64) {
            float4 v = *(const float4*)&Wq[(size_t)(col0 + lr + rr) * CN + k0 + lc];
            Bs[lc + 0][lr + rr] = v.x; Bs[lc + 1][lr + rr] = v.y;
            Bs[lc + 2][lr + rr] = v.z; Bs[lc + 3][lr + rr] = v.w;
        }
        __syncthreads();
#pragma unroll
        for (int kk = 0; kk < 16; kk++) {
            float a[8], b[8];
            *(float4*)&a[0] = *(const float4*)&As[kk][ty * 8];
            *(float4*)&a[4] = *(const float4*)&As[kk][ty * 8 + 4];
            *(float4*)&b[0] = *(const float4*)&Bs[kk][tx * 8];
            *(float4*)&b[4] = *(const float4*)&Bs[kk][tx * 8 + 4];
#pragma unroll
            for (int i = 0; i < 8; i++)
#pragma unroll
                for (int j = 0; j < 8; j++) acc[i][j] += a[i] * b[j];
        }
        __syncthreads();
    }

#pragma unroll
    for (int i = 0; i < 8; i++) {
        const int m   = row0 + ty * 8 + i;
        const int bb  = m >> 5;
        const int blk = m & 31;
        const size_t xoff = ((size_t)bb * CT + blk * S_ + jstep) * CN;
#pragma unroll
        for (int j = 0; j < 8; j += 4) {
            const int n = col0 + tx * 8 + j;
            float4 x = *(const float4*)&Xp[xoff + n];
            float4 v = make_float4(acc[i][j] + x.x, acc[i][j + 1] + x.y,
                                   acc[i][j + 2] + x.z, acc[i][j + 3] + x.w);
            *(float4*)&Sout[(size_t)m * CN + n] = v;
            if (STOREXP) *(float4*)&Xp[xoff + n] = v;
        }
    }
}

// =====================================================================
// Boundary step (split-K, deterministic): part[ks][64,1024] = A @ P^T (K-chunk ks)
// A = b_{k-1} [64,1024], P = Waa^16 [1024,1024] (row n = output feature).
// grid (16 n-tiles, 8 k-splits of 128), 256 threads, 64x64 tile, 4x4 microtile.
// =====================================================================
__global__ __launch_bounds__(256) void bstep_k(
    const float* __restrict__ A, const float* __restrict__ P,
    float* __restrict__ part)
{
    __shared__ float As[16][68];
    __shared__ float Bs[16][68];
    const int tid   = threadIdx.x;
    const int tx    = tid & 15, ty = tid >> 4;
    const int col0  = blockIdx.x * 64;
    const int kbase = blockIdx.y * 128;
    const int lr    = tid >> 2;          // 0..63
    const int lc    = (tid & 3) << 2;

    float acc[4][4];
#pragma unroll
    for (int i = 0; i < 4; i++)
#pragma unroll
        for (int j = 0; j < 4; j++) acc[i][j] = 0.f;

    for (int k0 = kbase; k0 < kbase + 128; k0 += 16) {
        {
            float4 v = *(const float4*)&A[(size_t)lr * CN + k0 + lc];
            As[lc + 0][lr] = v.x; As[lc + 1][lr] = v.y;
            As[lc + 2][lr] = v.z; As[lc + 3][lr] = v.w;
        }
        {
            float4 v = *(const float4*)&P[(size_t)(col0 + lr) * CN + k0 + lc];
            Bs[lc + 0][lr] = v.x; Bs[lc + 1][lr] = v.y;
            Bs[lc + 2][lr] = v.z; Bs[lc + 3][lr] = v.w;
        }
        __syncthreads();
#pragma unroll
        for (int kk = 0; kk < 16; kk++) {
            float a[4], b[4];
            *(float4*)&a[0] = *(const float4*)&As[kk][ty * 4];
            *(float4*)&b[0] = *(const float4*)&Bs[kk][tx * 4];
#pragma unroll
            for (int i = 0; i < 4; i++)
#pragma unroll
                for (int j = 0; j < 4; j++) acc[i][j] += a[i] * b[j];
        }
        __syncthreads();
    }

    float* dst = part + (size_t)blockIdx.y * CB * CN;
#pragma unroll
    for (int i = 0; i < 4; i++) {
        const int m = ty * 4 + i;
        const int n = col0 + tx * 4;
        *(float4*)&dst[(size_t)m * CN + n] =
            make_float4(acc[i][0], acc[i][1], acc[i][2], acc[i][3]);
    }
}

// b_k[m,n] = e_k[m,n] + sum_{s<8} part[s][m,n]   (e_k gathered from scan state)
__global__ __launch_bounds__(256) void breduce_k(
    float* __restrict__ Bk, const float* __restrict__ E, int k,
    const float* __restrict__ part)
{
    const size_t e = ((size_t)blockIdx.x * 256 + threadIdx.x) * 4; // 64 blocks -> 65536 floats
    const int bb = (int)(e >> 10);
    const int n  = (int)(e & 1023);
    float4 v = *(const float4*)&E[((size_t)(bb * NBLK + k)) * CN + n];
#pragma unroll
    for (int s = 0; s < 8; s++) {
        float4 p = *(const float4*)&part[(size_t)s * CB * CN + e];
        v.x += p.x; v.y += p.y; v.z += p.z; v.w += p.w;
    }
    *(float4*)&Bk[e] = v;
}

// b_0 = e_0 (plain gather copy)
__global__ __launch_bounds__(256) void binit_k(
    float* __restrict__ Bk, const float* __restrict__ E, int k)
{
    const size_t e = ((size_t)blockIdx.x * 256 + threadIdx.x) * 4;
    const int bb = (int)(e >> 10);
    const int n  = (int)(e & 1023);
    *(float4*)&Bk[e] = *(const float4*)&E[((size_t)(bb * NBLK + k)) * CN + n];
}

// pass-1 init: S[r,:] = Xp[t = blk*16, :]  (j=0 step with zero state is just a copy)
__global__ __launch_bounds__(256) void init_pass1_k(
    float* __restrict__ S, const float* __restrict__ Xp)
{
    const size_t e = ((size_t)blockIdx.x * 256 + threadIdx.x) * 4; // 2048 blocks
    const int r = (int)(e >> 10), n = (int)(e & 1023);
    const int bb = r >> 5, blk = r & 31;
    const size_t xrow = (size_t)bb * CT + blk * S_;
    *(float4*)&S[e] = *(const float4*)&Xp[xrow * CN + n];
}

// pass-3 init: S[r,:] = (blk==0) ? 0 : b_{blk-1}[bb,:]
__global__ __launch_bounds__(256) void init_pass3_k(
    float* __restrict__ S, const float* __restrict__ Bd)
{
    const size_t e = ((size_t)blockIdx.x * 256 + threadIdx.x) * 4;
    const int r = (int)(e >> 10), n = (int)(e & 1023);
    const int bb = r >> 5, blk = r & 31;
    float4 v = make_float4(0.f, 0.f, 0.f, 0.f);
    if (blk) v = *(const float4*)&Bd[((size_t)(blk - 1) * CB + bb) * CN + n];
    *(float4*)&S[e] = v;
}

// =====================================================================
extern "C" void kernel_launch(void* const* d_in, const int* in_sizes, int n_in,
                              void* d_out, int out_size)
{
    const float* X   = (const float*)d_in[0];
    const float* Wax = (const float*)d_in[1];
    const float* Waa = (const float*)d_in[2];
    const float* ba  = (const float*)d_in[3];
    const float* Wy  = (const float*)d_in[4];
    const float* by  = (const float*)d_in[5];
    float* Y = (float*)d_out;

    float *xp, *s1, *s2, *bd, *pA, *pB, *part;
    cudaGetSymbolAddress((void**)&xp,   g_xp);
    cudaGetSymbolAddress((void**)&s1,   g_s1);
    cudaGetSymbolAddress((void**)&s2,   g_s2);
    cudaGetSymbolAddress((void**)&bd,   g_bd);
    cudaGetSymbolAddress((void**)&pA,   g_pA);
    cudaGetSymbolAddress((void**)&pB,   g_pB);
    cudaGetSymbolAddress((void**)&part, g_part);

    // Phase A: Xp = X @ Wax^T + ba   [32768,1024] x [1024,1024]
    sgemm_k<1><<<dim3(CN / 128, MROWS / 128), 256>>>(X, Wax, ba, xp, MROWS, CN, CD);

    // Pass 1: in-block recurrence with zero init, all 32 blocks batched (M=2048)
    init_pass1_k<<<(MST * CN) / (4 * 256), 256>>>(s1, xp);
    float* cur = s1;
    float* nxt = s2;
    for (int j = 1; j < S_; j++) {
        step_k<0><<<dim3(CN / 128, MST / 128), 256>>>(cur, Waa, xp, j, nxt);
        float* t = cur; cur = nxt; nxt = t;
    }
    // cur now holds e_k = block-final states (r = bb*32 + blk)

    // Waa^16 via 4 squarings (NN matmuls)
    sgemm_k<0><<<dim3(8, 8), 256>>>(Waa, Waa, nullptr, pA, CN, CN, CN); // ^2
    sgemm_k<0><<<dim3(8, 8), 256>>>(pA,  pA,  nullptr, pB, CN, CN, CN); // ^4
    sgemm_k<0><<<dim3(8, 8), 256>>>(pB,  pB,  nullptr, pA, CN, CN, CN); // ^8
    sgemm_k<0><<<dim3(8, 8), 256>>>(pA,  pA,  nullptr, pB, CN, CN, CN); // ^16 -> pB

    // Boundary scan: b_0 = e_0; b_k = e_k + b_{k-1} @ (Waa^16)^T
    binit_k<<<64, 256>>>(bd, cur, 0);
    for (int k = 1; k < NBLK; k++) {
        bstep_k<<<dim3(16, 8), 256>>>(bd + (size_t)(k - 1) * CB * CN, pB, part);
        breduce_k<<<64, 256>>>(bd + (size_t)k * CB * CN, cur, k, part);
    }

    // Pass 3: re-run blocks seeded with boundary states; write a_t in-place over Xp
    float* c3 = (cur == s1) ? s2 : s1;  // the free ping-pong buffer
    float* n3 = cur;                    // e no longer needed after boundary scan
    init_pass3_k<<<(MST * CN) / (4 * 256), 256>>>(c3, bd);
    for (int j = 0; j < S_; j++) {
        step_k<1><<<dim3(CN / 128, MST / 128), 256>>>(c3, Waa, xp, j, n3);
        float* t = c3; c3 = n3; n3 = t;
    }

    // Phase Y: Y = A @ Wy^T + by  (A lives in xp now), straight into d_out
    sgemm_k<1><<<dim3(CN / 128, MROWS / 128), 256>>>(xp, Wy, by, Y, MROWS, CN, CN);
}

// round 3
// speedup vs baseline: 2.0609x; 2.0609x over previous
#include <cuda_runtime.h>
#include <cuda_bf16.h>
#include <cstdint>

// ---------------- problem constants ----------------
#define CB   64
#define CT   512
#define CD   1024
#define CN   1024
#define S_   16
#define NBLK 32
#define MROWS (CB * CT)    // 32768
#define MST   (CB * NBLK)  // 2048

// ---------------- scratch ----------------
__device__ float          g_xp [(size_t)MROWS * CN];
__device__ __nv_bfloat16  g_xch[(size_t)MROWS * CN];
__device__ __nv_bfloat16  g_xcl[(size_t)MROWS * CN];
__device__ __nv_bfloat16  g_ah [(size_t)MROWS * CN];
__device__ __nv_bfloat16  g_al [(size_t)MROWS * CN];
__device__ float          g_s1 [(size_t)MST * CN];
__device__ __nv_bfloat16  g_p1h[(size_t)MST * CN];
__device__ __nv_bfloat16  g_p1l[(size_t)MST * CN];
__device__ __nv_bfloat16  g_p2h[(size_t)MST * CN];
__device__ __nv_bfloat16  g_p2l[(size_t)MST * CN];
__device__ __nv_bfloat16  g_wxh[(size_t)CN * CN], g_wxl[(size_t)CN * CN];
__device__ __nv_bfloat16  g_wah[(size_t)CN * CN], g_wal[(size_t)CN * CN];
__device__ __nv_bfloat16  g_wyh[(size_t)CN * CN], g_wyl[(size_t)CN * CN];
__device__ float g_bd[(size_t)NBLK * CB * CN];
__device__ float g_pA[(size_t)CN * CN];
__device__ float g_pB[(size_t)CN * CN];
__device__ float g_part[(size_t)8 * CB * CN];

// =====================================================================
// Portable PTX helpers (sm_80-class features only — NO 'a'-suffix ops)
// =====================================================================
__device__ __forceinline__ uint32_t smem_u32(const void* p) {
    return (uint32_t)__cvta_generic_to_shared(p);
}
__device__ __forceinline__ void cp16(uint32_t dst, const void* src) {
    asm volatile("cp.async.cg.shared.global [%0], [%1], 16;\n" :: "r"(dst), "l"(src));
}
__device__ __forceinline__ void cp_commit() {
    asm volatile("cp.async.commit_group;\n" ::: "memory");
}
__device__ __forceinline__ void cp_wait0() {
    asm volatile("cp.async.wait_group 0;\n" ::: "memory");
}
__device__ __forceinline__ void ldsm4(uint32_t& r0, uint32_t& r1, uint32_t& r2, uint32_t& r3, uint32_t a) {
    asm volatile("ldmatrix.sync.aligned.m8n8.x4.shared.b16 {%0,%1,%2,%3}, [%4];\n"
                 : "=r"(r0), "=r"(r1), "=r"(r2), "=r"(r3) : "r"(a));
}
__device__ __forceinline__ void mma16816(float* d, const uint32_t* a, uint32_t b0, uint32_t b1) {
    asm volatile(
        "mma.sync.aligned.m16n8k16.row.col.f32.bf16.bf16.f32 "
        "{%0,%1,%2,%3}, {%4,%5,%6,%7}, {%8,%9}, {%0,%1,%2,%3};\n"
        : "+f"(d[0]), "+f"(d[1]), "+f"(d[2]), "+f"(d[3])
        : "r"(a[0]), "r"(a[1]), "r"(a[2]), "r"(a[3]), "r"(b0), "r"(b1));
}

// smem tile geometry: 128 rows x 32 bf16, padded to 40 bf16 (80B) per row
#define TROW   40
#define TILE_B (128 * TROW * 2)   // 10240 bytes
#define STAGE_B (4 * TILE_B)      // Ah, Al, Bh, Bl
#define SMEM_BYTES (2 * STAGE_B)  // 81920

// ---------------- per-stage global->smem loads (cp.async) ----------------
__device__ __forceinline__ void stage_load(
    uint32_t sbase, int buf,
    const __nv_bfloat16* __restrict__ Ah, const __nv_bfloat16* __restrict__ Al,
    const __nv_bfloat16* __restrict__ Bh, const __nv_bfloat16* __restrict__ Bl,
    int row0, int col0, int k0, int tid)
{
    const __nv_bfloat16* gp0 = Ah + (size_t)row0 * CN + k0;
    const __nv_bfloat16* gp1 = Al + (size_t)row0 * CN + k0;
    const __nv_bfloat16* gp2 = Bh + (size_t)col0 * CN + k0;
    const __nv_bfloat16* gp3 = Bl + (size_t)col0 * CN + k0;
    uint32_t base = sbase + buf * STAGE_B;
#pragma unroll
    for (int u = 0; u < 2; u++) {
        int e = tid + u * 256;          // 0..511
        int r = e >> 2, cu = e & 3;
        uint32_t off = (uint32_t)(r * (TROW * 2) + cu * 16);
        size_t gs = (size_t)r * CN + cu * 8;
        cp16(base + 0 * TILE_B + off, gp0 + gs);
        cp16(base + 1 * TILE_B + off, gp1 + gs);
        cp16(base + 2 * TILE_B + off, gp2 + gs);
        cp16(base + 3 * TILE_B + off, gp3 + gs);
    }
}

// ---------------- per-stage compute: 3-term bf16 MMA ----------------
__device__ __forceinline__ void stage_compute(
    uint32_t sbase, int buf, int wm, int wn, int lane, float acc[4][4][4])
{
    const uint32_t b0 = sbase + buf * STAGE_B;
    const uint32_t aH = b0, aL = b0 + TILE_B, bH = b0 + 2 * TILE_B, bL = b0 + 3 * TILE_B;
    const int arow = wm * 64 + (lane & 15);
    const int brow = wn * 32 + (lane & 7) + ((lane >> 4) & 1) * 8;
#pragma unroll
    for (int k16 = 0; k16 < 2; k16++) {
        const int akc = k16 * 16 + (lane >> 4) * 8;
        const int bkc = k16 * 16 + ((lane >> 3) & 1) * 8;
        uint32_t af[4][4], bh[2][4], bl[2][4];
#pragma unroll
        for (int mi = 0; mi < 4; mi++)
            ldsm4(af[mi][0], af[mi][1], af[mi][2], af[mi][3],
                  aH + (uint32_t)((arow + mi * 16) * (TROW * 2) + akc * 2));
#pragma unroll
        for (int nf = 0; nf < 2; nf++)
            ldsm4(bh[nf][0], bh[nf][1], bh[nf][2], bh[nf][3],
                  bH + (uint32_t)((brow + nf * 16) * (TROW * 2) + bkc * 2));
#pragma unroll
        for (int nf = 0; nf < 2; nf++)
            ldsm4(bl[nf][0], bl[nf][1], bl[nf][2], bl[nf][3],
                  bL + (uint32_t)((brow + nf * 16) * (TROW * 2) + bkc * 2));
        // hh + hl terms
#pragma unroll
        for (int mi = 0; mi < 4; mi++)
#pragma unroll
            for (int nf = 0; nf < 2; nf++)
#pragma unroll
                for (int sub = 0; sub < 2; sub++) {
                    mma16816(acc[mi][nf * 2 + sub], af[mi], bh[nf][sub * 2], bh[nf][sub * 2 + 1]);
                    mma16816(acc[mi][nf * 2 + sub], af[mi], bl[nf][sub * 2], bl[nf][sub * 2 + 1]);
                }
        // lh term: reload A-lo frags (reuses af liveness)
#pragma unroll
        for (int mi = 0; mi < 4; mi++)
            ldsm4(af[mi][0], af[mi][1], af[mi][2], af[mi][3],
                  aL + (uint32_t)((arow + mi * 16) * (TROW * 2) + akc * 2));
#pragma unroll
        for (int mi = 0; mi < 4; mi++)
#pragma unroll
            for (int nf = 0; nf < 2; nf++)
#pragma unroll
                for (int sub = 0; sub < 2; sub++)
                    mma16816(acc[mi][nf * 2 + sub], af[mi], bh[nf][sub * 2], bh[nf][sub * 2 + 1]);
    }
}

// =====================================================================
// Fused GEMM kernel.  EPI=0: out = acc + bias (fp32).
// EPI=1: step epilogue: v = acc + xp[t(m)]; split to hi/lo state planes;
//        WF32 -> also fp32 E;  WA -> also big A hi/lo planes at time-major row.
// =====================================================================
template <int EPI, bool WF32, bool WA>
__global__ __launch_bounds__(256) void mma_gemm(
    const __nv_bfloat16* __restrict__ Ah, const __nv_bfloat16* __restrict__ Al,
    const __nv_bfloat16* __restrict__ Bh, const __nv_bfloat16* __restrict__ Bl,
    const float* __restrict__ aux,   // bias (EPI0) or xp (EPI1)
    int jstep,
    float* __restrict__ f32out,
    __nv_bfloat16* __restrict__ sh, __nv_bfloat16* __restrict__ sl,
    __nv_bfloat16* __restrict__ oah, __nv_bfloat16* __restrict__ oal)
{
    extern __shared__ char smem[];
    const uint32_t sbase = smem_u32(smem);
    const int tid = threadIdx.x, lane = tid & 31, w = tid >> 5;
    const int wm = w & 1, wn = w >> 1;
    const int row0 = blockIdx.y * 128, col0 = blockIdx.x * 128;

    float acc[4][4][4];
#pragma unroll
    for (int i = 0; i < 4; i++)
#pragma unroll
        for (int j = 0; j < 4; j++)
#pragma unroll
            for (int r = 0; r < 4; r++) acc[i][j][r] = 0.f;

    stage_load(sbase, 0, Ah, Al, Bh, Bl, row0, col0, 0, tid);
    cp_commit();
    const int NS = CN / 32;  // 32 stages
    for (int s = 0; s < NS; s++) {
        cp_wait0();
        __syncthreads();
        if (s + 1 < NS) {
            stage_load(sbase, (s + 1) & 1, Ah, Al, Bh, Bl, row0, col0, (s + 1) * 32, tid);
            cp_commit();
        }
        stage_compute(sbase, s & 1, wm, wn, lane, acc);
        __syncthreads();
    }

    // ---------------- epilogue ----------------
#pragma unroll
    for (int mi = 0; mi < 4; mi++) {
        const int rbase = row0 + wm * 64 + mi * 16 + (lane >> 2);
#pragma unroll
        for (int half = 0; half < 2; half++) {
            const int m = rbase + half * 8;
#pragma unroll
            for (int ni = 0; ni < 4; ni++) {
                const int c = col0 + wn * 32 + ni * 8 + (lane & 3) * 2;
                float v0 = acc[mi][ni][half * 2 + 0];
                float v1 = acc[mi][ni][half * 2 + 1];
                if (EPI == 0) {
                    v0 += aux[c]; v1 += aux[c + 1];
                    *(float2*)&f32out[(size_t)m * CN + c] = make_float2(v0, v1);
                } else {
                    const int bb = m >> 5, blk = m & 31;
                    const size_t xoff = ((size_t)bb * CT + blk * S_ + jstep) * CN;
                    float2 x = *(const float2*)&aux[xoff + c];
                    v0 += x.x; v1 += x.y;
                    if (WF32)
                        *(float2*)&f32out[(size_t)m * CN + c] = make_float2(v0, v1);
                    __nv_bfloat162 h, l;
                    h.x = __float2bfloat16(v0); l.x = __float2bfloat16(v0 - __bfloat162float(h.x));
                    h.y = __float2bfloat16(v1); l.y = __float2bfloat16(v1 - __bfloat162float(h.y));
                    *(__nv_bfloat162*)&sh[(size_t)m * CN + c] = h;
                    *(__nv_bfloat162*)&sl[(size_t)m * CN + c] = l;
                    if (WA) {
                        *(__nv_bfloat162*)&oah[xoff + c] = h;
                        *(__nv_bfloat162*)&oal[xoff + c] = l;
                    }
                }
            }
        }
    }
}

// ---------------- fp32 -> bf16 hi/lo split ----------------
__global__ __launch_bounds__(256) void split_k(
    const float* __restrict__ src, __nv_bfloat16* __restrict__ hi, __nv_bfloat16* __restrict__ lo)
{
    const size_t e = ((size_t)blockIdx.x * 256 + threadIdx.x) * 4;
    float4 v = *(const float4*)&src[e];
    __nv_bfloat162 h0, h1, l0, l1;
    h0.x = __float2bfloat16(v.x); l0.x = __float2bfloat16(v.x - __bfloat162float(h0.x));
    h0.y = __float2bfloat16(v.y); l0.y = __float2bfloat16(v.y - __bfloat162float(h0.y));
    h1.x = __float2bfloat16(v.z); l1.x = __float2bfloat16(v.z - __bfloat162float(h1.x));
    h1.y = __float2bfloat16(v.w); l1.y = __float2bfloat16(v.w - __bfloat162float(h1.y));
    *(__nv_bfloat162*)&hi[e] = h0; *(__nv_bfloat162*)&hi[e + 2] = h1;
    *(__nv_bfloat162*)&lo[e] = l0; *(__nv_bfloat162*)&lo[e + 2] = l1;
}

// pass-1 init: state row r = Xp[t = blk*16] split to planes
__global__ __launch_bounds__(256) void init1_split_k(
    const float* __restrict__ xp, __nv_bfloat16* __restrict__ hi, __nv_bfloat16* __restrict__ lo)
{
    const size_t e = ((size_t)blockIdx.x * 256 + threadIdx.x) * 4;
    const int r = (int)(e >> 10), n = (int)(e & 1023);
    const int bb = r >> 5, blk = r & 31;
    float4 v = *(const float4*)&xp[((size_t)bb * CT + blk * S_) * CN + n];
    __nv_bfloat162 h0, h1, l0, l1;
    h0.x = __float2bfloat16(v.x); l0.x = __float2bfloat16(v.x - __bfloat162float(h0.x));
    h0.y = __float2bfloat16(v.y); l0.y = __float2bfloat16(v.y - __bfloat162float(h0.y));
    h1.x = __float2bfloat16(v.z); l1.x = __float2bfloat16(v.z - __bfloat162float(h1.x));
    h1.y = __float2bfloat16(v.w); l1.y = __float2bfloat16(v.w - __bfloat162float(h1.y));
    *(__nv_bfloat162*)&hi[e] = h0; *(__nv_bfloat162*)&hi[e + 2] = h1;
    *(__nv_bfloat162*)&lo[e] = l0; *(__nv_bfloat162*)&lo[e + 2] = l1;
}

// pass-3 init: state row r = (blk ? bd[blk-1][bb] : 0) split to planes
__global__ __launch_bounds__(256) void init3_split_k(
    const float* __restrict__ bd, __nv_bfloat16* __restrict__ hi, __nv_bfloat16* __restrict__ lo)
{
    const size_t e = ((size_t)blockIdx.x * 256 + threadIdx.x) * 4;
    const int r = (int)(e >> 10), n = (int)(e & 1023);
    const int bb = r >> 5, blk = r & 31;
    float4 v = make_float4(0.f, 0.f, 0.f, 0.f);
    if (blk) v = *(const float4*)&bd[((size_t)(blk - 1) * CB + bb) * CN + n];
    __nv_bfloat162 h0, h1, l0, l1;
    h0.x = __float2bfloat16(v.x); l0.x = __float2bfloat16(v.x - __bfloat162float(h0.x));
    h0.y = __float2bfloat16(v.y); l0.y = __float2bfloat16(v.y - __bfloat162float(h0.y));
    h1.x = __float2bfloat16(v.z); l1.x = __float2bfloat16(v.z - __bfloat162float(h1.x));
    h1.y = __float2bfloat16(v.w); l1.y = __float2bfloat16(v.w - __bfloat162float(h1.y));
    *(__nv_bfloat162*)&hi[e] = h0; *(__nv_bfloat162*)&hi[e + 2] = h1;
    *(__nv_bfloat162*)&lo[e] = l0; *(__nv_bfloat162*)&lo[e + 2] = l1;
}

// =====================================================================
// fp32 kernels for squarings + boundary scan (small work, full precision)
// =====================================================================
__global__ __launch_bounds__(256) void sgemm_nn_k(
    const float* __restrict__ A, const float* __restrict__ W, float* __restrict__ C)
{
    __shared__ float As[16][132];
    __shared__ float Bs[16][132];
    const int tid = threadIdx.x;
    const int tx = tid & 15, ty = tid >> 4;
    const int row0 = blockIdx.y * 128, col0 = blockIdx.x * 128;
    const int lr = tid >> 2, lc = (tid & 3) << 2;
    float acc[8][8];
#pragma unroll
    for (int i = 0; i < 8; i++)
#pragma unroll
        for (int j = 0; j < 8; j++) acc[i][j] = 0.f;
    for (int k0 = 0; k0 < CN; k0 += 16) {
#pragma unroll
        for (int rr = 0; rr < 128; rr += 64) {
            float4 v = *(const float4*)&A[(size_t)(row0 + lr + rr) * CN + k0 + lc];
            As[lc + 0][lr + rr] = v.x; As[lc + 1][lr + rr] = v.y;
            As[lc + 2][lr + rr] = v.z; As[lc + 3][lr + rr] = v.w;
        }
        {
            const int kr = tid >> 5;
            const int nc = (tid & 31) << 2;
#pragma unroll
            for (int rr = 0; rr < 16; rr += 8) {
                float4 v = *(const float4*)&W[(size_t)(k0 + kr + rr) * CN + col0 + nc];
                *(float4*)&Bs[kr + rr][nc] = v;
            }
        }
        __syncthreads();
#pragma unroll
        for (int kk = 0; kk < 16; kk++) {
            float a[8], b[8];
            *(float4*)&a[0] = *(const float4*)&As[kk][ty * 8];
            *(float4*)&a[4] = *(const float4*)&As[kk][ty * 8 + 4];
            *(float4*)&b[0] = *(const float4*)&Bs[kk][tx * 8];
            *(float4*)&b[4] = *(const float4*)&Bs[kk][tx * 8 + 4];
#pragma unroll
            for (int i = 0; i < 8; i++)
#pragma unroll
                for (int j = 0; j < 8; j++) acc[i][j] += a[i] * b[j];
        }
        __syncthreads();
    }
#pragma unroll
    for (int i = 0; i < 8; i++) {
        const size_t m = (size_t)row0 + ty * 8 + i;
#pragma unroll
        for (int j = 0; j < 8; j += 4) {
            const int n = col0 + tx * 8 + j;
            *(float4*)&C[m * CN + n] =
                make_float4(acc[i][j], acc[i][j + 1], acc[i][j + 2], acc[i][j + 3]);
        }
    }
}

__global__ __launch_bounds__(256) void bstep_k(
    const float* __restrict__ A, const float* __restrict__ P, float* __restrict__ part)
{
    __shared__ float As[16][68];
    __shared__ float Bs[16][68];
    const int tid = threadIdx.x;
    const int tx = tid & 15, ty = tid >> 4;
    const int col0 = blockIdx.x * 64;
    const int kbase = blockIdx.y * 128;
    const int lr = tid >> 2, lc = (tid & 3) << 2;
    float acc[4][4];
#pragma unroll
    for (int i = 0; i < 4; i++)
#pragma unroll
        for (int j = 0; j < 4; j++) acc[i][j] = 0.f;
    for (int k0 = kbase; k0 < kbase + 128; k0 += 16) {
        {
            float4 v = *(const float4*)&A[(size_t)lr * CN + k0 + lc];
            As[lc + 0][lr] = v.x; As[lc + 1][lr] = v.y; As[lc + 2][lr] = v.z; As[lc + 3][lr] = v.w;
        }
        {
            float4 v = *(const float4*)&P[(size_t)(col0 + lr) * CN + k0 + lc];
            Bs[lc + 0][lr] = v.x; Bs[lc + 1][lr] = v.y; Bs[lc + 2][lr] = v.z; Bs[lc + 3][lr] = v.w;
        }
        __syncthreads();
#pragma unroll
        for (int kk = 0; kk < 16; kk++) {
            float a[4], b[4];
            *(float4*)&a[0] = *(const float4*)&As[kk][ty * 4];
            *(float4*)&b[0] = *(const float4*)&Bs[kk][tx * 4];
#pragma unroll
            for (int i = 0; i < 4; i++)
#pragma unroll
                for (int j = 0; j < 4; j++) acc[i][j] += a[i] * b[j];
        }
        __syncthreads();
    }
    float* dst = part + (size_t)blockIdx.y * CB * CN;
#pragma unroll
    for (int i = 0; i < 4; i++) {
        const int m = ty * 4 + i;
        const int n = col0 + tx * 4;
        *(float4*)&dst[(size_t)m * CN + n] = make_float4(acc[i][0], acc[i][1], acc[i][2], acc[i][3]);
    }
}

__global__ __launch_bounds__(256) void breduce_k(
    float* __restrict__ Bk, const float* __restrict__ E, int k, const float* __restrict__ part)
{
    const size_t e = ((size_t)blockIdx.x * 256 + threadIdx.x) * 4;
    const int bb = (int)(e >> 10);
    const int n = (int)(e & 1023);
    float4 v = *(const float4*)&E[((size_t)(bb * NBLK + k)) * CN + n];
#pragma unroll
    for (int s = 0; s < 8; s++) {
        float4 p = *(const float4*)&part[(size_t)s * CB * CN + e];
        v.x += p.x; v.y += p.y; v.z += p.z; v.w += p.w;
    }
    *(float4*)&Bk[e] = v;
}

__global__ __launch_bounds__(256) void binit_k(
    float* __restrict__ Bk, const float* __restrict__ E, int k)
{
    const size_t e = ((size_t)blockIdx.x * 256 + threadIdx.x) * 4;
    const int bb = (int)(e >> 10);
    const int n = (int)(e & 1023);
    *(float4*)&Bk[e] = *(const float4*)&E[((size_t)(bb * NBLK + k)) * CN + n];
}

// =====================================================================
// host
// =====================================================================
extern "C" void kernel_launch(void* const* d_in, const int* in_sizes, int n_in,
                              void* d_out, int out_size)
{
    const float* X   = (const float*)d_in[0];
    const float* Wax = (const float*)d_in[1];
    const float* Waa = (const float*)d_in[2];
    const float* ba  = (const float*)d_in[3];
    const float* Wy  = (const float*)d_in[4];
    const float* by  = (const float*)d_in[5];
    float* Y = (float*)d_out;

    void *xpv, *xchv, *xclv, *ahv, *alv, *s1v, *p1hv, *p1lv, *p2hv, *p2lv;
    void *wxhv, *wxlv, *wahv, *walv, *wyhv, *wylv, *bdv, *pAv, *pBv, *partv;
    cudaGetSymbolAddress(&xpv, g_xp);   cudaGetSymbolAddress(&xchv, g_xch);
    cudaGetSymbolAddress(&xclv, g_xcl); cudaGetSymbolAddress(&ahv, g_ah);
    cudaGetSymbolAddress(&alv, g_al);   cudaGetSymbolAddress(&s1v, g_s1);
    cudaGetSymbolAddress(&p1hv, g_p1h); cudaGetSymbolAddress(&p1lv, g_p1l);
    cudaGetSymbolAddress(&p2hv, g_p2h); cudaGetSymbolAddress(&p2lv, g_p2l);
    cudaGetSymbolAddress(&wxhv, g_wxh); cudaGetSymbolAddress(&wxlv, g_wxl);
    cudaGetSymbolAddress(&wahv, g_wah); cudaGetSymbolAddress(&walv, g_wal);
    cudaGetSymbolAddress(&wyhv, g_wyh); cudaGetSymbolAddress(&wylv, g_wyl);
    cudaGetSymbolAddress(&bdv, g_bd);   cudaGetSymbolAddress(&pAv, g_pA);
    cudaGetSymbolAddress(&pBv, g_pB);   cudaGetSymbolAddress(&partv, g_part);

    float* xp = (float*)xpv; float* s1 = (float*)s1v;
    float* bd = (float*)bdv; float* pA = (float*)pAv; float* pB = (float*)pBv;
    float* part = (float*)partv;
    __nv_bfloat16* xch = (__nv_bfloat16*)xchv; __nv_bfloat16* xcl = (__nv_bfloat16*)xclv;
    __nv_bfloat16* ah  = (__nv_bfloat16*)ahv;  __nv_bfloat16* al  = (__nv_bfloat16*)alv;
    __nv_bfloat16* p1h = (__nv_bfloat16*)p1hv; __nv_bfloat16* p1l = (__nv_bfloat16*)p1lv;
    __nv_bfloat16* p2h = (__nv_bfloat16*)p2hv; __nv_bfloat16* p2l = (__nv_bfloat16*)p2lv;
    __nv_bfloat16* wxh = (__nv_bfloat16*)wxhv; __nv_bfloat16* wxl = (__nv_bfloat16*)wxlv;
    __nv_bfloat16* wah = (__nv_bfloat16*)wahv; __nv_bfloat16* wal = (__nv_bfloat16*)walv;
    __nv_bfloat16* wyh = (__nv_bfloat16*)wyhv; __nv_bfloat16* wyl = (__nv_bfloat16*)wylv;

    cudaFuncSetAttribute(mma_gemm<0, false, false>, cudaFuncAttributeMaxDynamicSharedMemorySize, SMEM_BYTES);
    cudaFuncSetAttribute(mma_gemm<1, false, false>, cudaFuncAttributeMaxDynamicSharedMemorySize, SMEM_BYTES);
    cudaFuncSetAttribute(mma_gemm<1, true,  false>, cudaFuncAttributeMaxDynamicSharedMemorySize, SMEM_BYTES);
    cudaFuncSetAttribute(mma_gemm<1, false, true >, cudaFuncAttributeMaxDynamicSharedMemorySize, SMEM_BYTES);

    // ---- splits ----
    split_k<<<(MROWS * CN) / 1024, 256>>>(X, xch, xcl);
    split_k<<<(CN * CN) / 1024, 256>>>(Wax, wxh, wxl);
    split_k<<<(CN * CN) / 1024, 256>>>(Waa, wah, wal);
    split_k<<<(CN * CN) / 1024, 256>>>(Wy, wyh, wyl);

    // ---- Phase A: Xp = X @ Wax^T + ba ----
    mma_gemm<0, false, false><<<dim3(CN / 128, MROWS / 128), 256, SMEM_BYTES>>>(
        xch, xcl, wxh, wxl, ba, 0, xp, nullptr, nullptr, nullptr, nullptr);

    // ---- Pass 1: 15 batched steps (M=2048) ----
    init1_split_k<<<(MST * CN) / 1024, 256>>>(xp, p1h, p1l);
    for (int j = 1; j < S_; j++) {
        bool in1 = (j & 1);
        __nv_bfloat16* iah = in1 ? p1h : p2h;
        __nv_bfloat16* ial = in1 ? p1l : p2l;
        __nv_bfloat16* oh  = in1 ? p2h : p1h;
        __nv_bfloat16* ol  = in1 ? p2l : p1l;
        if (j == S_ - 1)
            mma_gemm<1, true, false><<<dim3(CN / 128, MST / 128), 256, SMEM_BYTES>>>(
                iah, ial, wah, wal, xp, j, s1, oh, ol, nullptr, nullptr);
        else
            mma_gemm<1, false, false><<<dim3(CN / 128, MST / 128), 256, SMEM_BYTES>>>(
                iah, ial, wah, wal, xp, j, nullptr, oh, ol, nullptr, nullptr);
    }

    // ---- Waa^16 via 4 squarings (fp32) ----
    sgemm_nn_k<<<dim3(8, 8), 256>>>(Waa, Waa, pA);
    sgemm_nn_k<<<dim3(8, 8), 256>>>(pA, pA, pB);
    sgemm_nn_k<<<dim3(8, 8), 256>>>(pB, pB, pA);
    sgemm_nn_k<<<dim3(8, 8), 256>>>(pA, pA, pB);

    // ---- Boundary scan (fp32, split-K) ----
    binit_k<<<64, 256>>>(bd, s1, 0);
    for (int k = 1; k < NBLK; k++) {
        bstep_k<<<dim3(16, 8), 256>>>(bd + (size_t)(k - 1) * CB * CN, pB, part);
        breduce_k<<<64, 256>>>(bd + (size_t)k * CB * CN, s1, k, part);
    }

    // ---- Pass 3: 16 steps, write a_t hi/lo planes ----
    init3_split_k<<<(MST * CN) / 1024, 256>>>(bd, p1h, p1l);
    for (int j = 0; j < S_; j++) {
        bool in1 = ((j & 1) == 0);
        __nv_bfloat16* iah = in1 ? p1h : p2h;
        __nv_bfloat16* ial = in1 ? p1l : p2l;
        __nv_bfloat16* oh  = in1 ? p2h : p1h;
        __nv_bfloat16* ol  = in1 ? p2l : p1l;
        mma_gemm<1, false, true><<<dim3(CN / 128, MST / 128), 256, SMEM_BYTES>>>(
            iah, ial, wah, wal, xp, j, nullptr, oh, ol, ah, al);
    }

    // ---- Phase Y: Y = A @ Wy^T + by ----
    mma_gemm<0, false, false><<<dim3(CN / 128, MROWS / 128), 256, SMEM_BYTES>>>(
        ah, al, wyh, wyl, by, 0, Y, nullptr, nullptr, nullptr, nullptr);
}

// round 4
// speedup vs baseline: 2.2275x; 1.0808x over previous
#include <cuda_runtime.h>
#include <cuda_bf16.h>
#include <cstdint>

// ---------------- problem constants ----------------
#define CB   64
#define CT   512
#define CD   1024
#define CN   1024
#define S_   16
#define NBLK 32
#define MROWS (CB * CT)    // 32768
#define MST   (CB * NBLK)  // 2048
#define NCTA  128          // persistent grid size (<= 148 SMs, one wave)

// ---------------- scratch ----------------
__device__ float          g_xp [(size_t)MROWS * CN];
__device__ __nv_bfloat16  g_xch[(size_t)MROWS * CN];
__device__ __nv_bfloat16  g_xcl[(size_t)MROWS * CN];
__device__ __nv_bfloat16  g_ah [(size_t)MROWS * CN];
__device__ __nv_bfloat16  g_al [(size_t)MROWS * CN];
__device__ float          g_s1 [(size_t)MST * CN];      // E states fp32
__device__ __nv_bfloat16  g_p1h[(size_t)MST * CN];
__device__ __nv_bfloat16  g_p1l[(size_t)MST * CN];
__device__ __nv_bfloat16  g_p2h[(size_t)MST * CN];
__device__ __nv_bfloat16  g_p2l[(size_t)MST * CN];
__device__ __nv_bfloat16  g_wxh[(size_t)CN * CN], g_wxl[(size_t)CN * CN];
__device__ __nv_bfloat16  g_wah[(size_t)CN * CN], g_wal[(size_t)CN * CN];
__device__ __nv_bfloat16  g_wyh[(size_t)CN * CN], g_wyl[(size_t)CN * CN];
__device__ __nv_bfloat16  g_wth[(size_t)CN * CN], g_wtl[(size_t)CN * CN]; // Waa^T planes
__device__ float g_bd[(size_t)NBLK * CB * CN];
__device__ float g_pA[(size_t)CN * CN];
__device__ float g_pB[(size_t)CN * CN];
__device__ float g_part[(size_t)8 * CB * CN];
__device__ unsigned g_cnt;
__device__ unsigned g_gen;

// =====================================================================
// Portable PTX helpers (sm_80-class only)
// =====================================================================
__device__ __forceinline__ uint32_t smem_u32(const void* p) {
    return (uint32_t)__cvta_generic_to_shared(p);
}
__device__ __forceinline__ void cp16(uint32_t dst, const void* src) {
    asm volatile("cp.async.cg.shared.global [%0], [%1], 16;\n" :: "r"(dst), "l"(src));
}
__device__ __forceinline__ void cp_commit() {
    asm volatile("cp.async.commit_group;\n" ::: "memory");
}
__device__ __forceinline__ void cp_wait0() {
    asm volatile("cp.async.wait_group 0;\n" ::: "memory");
}
__device__ __forceinline__ void ldsm4(uint32_t& r0, uint32_t& r1, uint32_t& r2, uint32_t& r3, uint32_t a) {
    asm volatile("ldmatrix.sync.aligned.m8n8.x4.shared.b16 {%0,%1,%2,%3}, [%4];\n"
                 : "=r"(r0), "=r"(r1), "=r"(r2), "=r"(r3) : "r"(a));
}
__device__ __forceinline__ void mma16816(float* d, const uint32_t* a, uint32_t b0, uint32_t b1) {
    asm volatile(
        "mma.sync.aligned.m16n8k16.row.col.f32.bf16.bf16.f32 "
        "{%0,%1,%2,%3}, {%4,%5,%6,%7}, {%8,%9}, {%0,%1,%2,%3};\n"
        : "+f"(d[0]), "+f"(d[1]), "+f"(d[2]), "+f"(d[3])
        : "r"(a[0]), "r"(a[1]), "r"(a[2]), "r"(a[3]), "r"(b0), "r"(b1));
}

// grid-wide barrier: sense-reversing, deterministic, replay-safe
__device__ __forceinline__ void grid_sync() {
    __syncthreads();
    if (threadIdx.x == 0) {
        __threadfence();
        volatile unsigned* gen = &g_gen;
        unsigned my = *gen;
        unsigned old = atomicAdd(&g_cnt, 1u);
        if (old == (unsigned)(NCTA - 1)) {
            g_cnt = 0u;
            __threadfence();
            *gen = my + 1u;
        } else {
            while (*gen == my) { }
        }
        __threadfence();
    }
    __syncthreads();
}

// smem tile geometry: 128 rows x 32 bf16, padded to 40 bf16/row
#define TROW   40
#define TILE_B (128 * TROW * 2)   // 10240 bytes
#define STAGE_B (4 * TILE_B)      // Ah, Al, Bh, Bl
#define SMEM_BYTES (2 * STAGE_B)  // 81920

// ---------------- per-stage global->smem loads (cp.async) ----------------
__device__ __forceinline__ void stage_load(
    uint32_t sbase, int buf,
    const __nv_bfloat16* __restrict__ Ah, const __nv_bfloat16* __restrict__ Al,
    const __nv_bfloat16* __restrict__ Bh, const __nv_bfloat16* __restrict__ Bl,
    int row0, int col0, int k0, int tid)
{
    const __nv_bfloat16* gp0 = Ah + (size_t)row0 * CN + k0;
    const __nv_bfloat16* gp1 = Al + (size_t)row0 * CN + k0;
    const __nv_bfloat16* gp2 = Bh + (size_t)col0 * CN + k0;
    const __nv_bfloat16* gp3 = Bl + (size_t)col0 * CN + k0;
    uint32_t base = sbase + buf * STAGE_B;
#pragma unroll
    for (int u = 0; u < 2; u++) {
        int e = tid + u * 256;
        int r = e >> 2, cu = e & 3;
        uint32_t off = (uint32_t)(r * (TROW * 2) + cu * 16);
        size_t gs = (size_t)r * CN + cu * 8;
        cp16(base + 0 * TILE_B + off, gp0 + gs);
        cp16(base + 1 * TILE_B + off, gp1 + gs);
        cp16(base + 2 * TILE_B + off, gp2 + gs);
        cp16(base + 3 * TILE_B + off, gp3 + gs);
    }
}

// ---------------- per-stage compute: 3-term bf16 MMA ----------------
__device__ __forceinline__ void stage_compute(
    uint32_t sbase, int buf, int wm, int wn, int lane, float acc[4][4][4])
{
    const uint32_t b0 = sbase + buf * STAGE_B;
    const uint32_t aH = b0, aL = b0 + TILE_B, bH = b0 + 2 * TILE_B, bL = b0 + 3 * TILE_B;
    const int arow = wm * 64 + (lane & 15);
    const int brow = wn * 32 + (lane & 7) + ((lane >> 4) & 1) * 8;
#pragma unroll
    for (int k16 = 0; k16 < 2; k16++) {
        const int akc = k16 * 16 + (lane >> 4) * 8;
        const int bkc = k16 * 16 + ((lane >> 3) & 1) * 8;
        uint32_t af[4][4], bh[2][4], bl[2][4];
#pragma unroll
        for (int mi = 0; mi < 4; mi++)
            ldsm4(af[mi][0], af[mi][1], af[mi][2], af[mi][3],
                  aH + (uint32_t)((arow + mi * 16) * (TROW * 2) + akc * 2));
#pragma unroll
        for (int nf = 0; nf < 2; nf++)
            ldsm4(bh[nf][0], bh[nf][1], bh[nf][2], bh[nf][3],
                  bH + (uint32_t)((brow + nf * 16) * (TROW * 2) + bkc * 2));
#pragma unroll
        for (int nf = 0; nf < 2; nf++)
            ldsm4(bl[nf][0], bl[nf][1], bl[nf][2], bl[nf][3],
                  bL + (uint32_t)((brow + nf * 16) * (TROW * 2) + bkc * 2));
#pragma unroll
        for (int mi = 0; mi < 4; mi++)
#pragma unroll
            for (int nf = 0; nf < 2; nf++)
#pragma unroll
                for (int sub = 0; sub < 2; sub++) {
                    mma16816(acc[mi][nf * 2 + sub], af[mi], bh[nf][sub * 2], bh[nf][sub * 2 + 1]);
                    mma16816(acc[mi][nf * 2 + sub], af[mi], bl[nf][sub * 2], bl[nf][sub * 2 + 1]);
                }
#pragma unroll
        for (int mi = 0; mi < 4; mi++)
            ldsm4(af[mi][0], af[mi][1], af[mi][2], af[mi][3],
                  aL + (uint32_t)((arow + mi * 16) * (TROW * 2) + akc * 2));
#pragma unroll
        for (int mi = 0; mi < 4; mi++)
#pragma unroll
            for (int nf = 0; nf < 2; nf++)
#pragma unroll
                for (int sub = 0; sub < 2; sub++)
                    mma16816(acc[mi][nf * 2 + sub], af[mi], bh[nf][sub * 2], bh[nf][sub * 2 + 1]);
    }
}

// ---------------- full K=1024 pipelined GEMM core ----------------
__device__ __forceinline__ void gemm_core(
    uint32_t sbase, int tid, int wm, int wn, int lane,
    const __nv_bfloat16* Ah, const __nv_bfloat16* Al,
    const __nv_bfloat16* Bh, const __nv_bfloat16* Bl,
    int row0, int col0, float acc[4][4][4])
{
#pragma unroll
    for (int i = 0; i < 4; i++)
#pragma unroll
        for (int j = 0; j < 4; j++)
#pragma unroll
            for (int r = 0; r < 4; r++) acc[i][j][r] = 0.f;
    stage_load(sbase, 0, Ah, Al, Bh, Bl, row0, col0, 0, tid);
    cp_commit();
    const int NS = CN / 32;
    for (int s = 0; s < NS; s++) {
        cp_wait0();
        __syncthreads();
        if (s + 1 < NS) {
            stage_load(sbase, (s + 1) & 1, Ah, Al, Bh, Bl, row0, col0, (s + 1) * 32, tid);
            cp_commit();
        }
        stage_compute(sbase, s & 1, wm, wn, lane, acc);
        __syncthreads();
    }
}

// ---------------- step epilogue (runtime flags) ----------------
__device__ __forceinline__ void step_epi(
    float acc[4][4][4], int row0, int col0, int wm, int wn, int lane,
    const float* __restrict__ xp, int jstep,
    float* __restrict__ f32out,
    __nv_bfloat16* __restrict__ sh, __nv_bfloat16* __restrict__ sl,
    __nv_bfloat16* __restrict__ oah, __nv_bfloat16* __restrict__ oal)
{
#pragma unroll
    for (int mi = 0; mi < 4; mi++) {
        const int rbase = row0 + wm * 64 + mi * 16 + (lane >> 2);
#pragma unroll
        for (int half = 0; half < 2; half++) {
            const int m = rbase + half * 8;
            const int bb = m >> 5, blk = m & 31;
            const size_t xoff = ((size_t)bb * CT + blk * S_ + jstep) * CN;
#pragma unroll
            for (int ni = 0; ni < 4; ni++) {
                const int c = col0 + wn * 32 + ni * 8 + (lane & 3) * 2;
                float2 x = *(const float2*)&xp[xoff + c];
                float v0 = acc[mi][ni][half * 2 + 0] + x.x;
                float v1 = acc[mi][ni][half * 2 + 1] + x.y;
                if (f32out)
                    *(float2*)&f32out[(size_t)m * CN + c] = make_float2(v0, v1);
                __nv_bfloat162 h, l;
                h.x = __float2bfloat16(v0); l.x = __float2bfloat16(v0 - __bfloat162float(h.x));
                h.y = __float2bfloat16(v1); l.y = __float2bfloat16(v1 - __bfloat162float(h.y));
                *(__nv_bfloat162*)&sh[(size_t)m * CN + c] = h;
                *(__nv_bfloat162*)&sl[(size_t)m * CN + c] = l;
                if (oah) {
                    *(__nv_bfloat162*)&oah[xoff + c] = h;
                    *(__nv_bfloat162*)&oal[xoff + c] = l;
                }
            }
        }
    }
}

// ---------------- helpers: split ----------------
__device__ __forceinline__ void split2(float v0, float v1, __nv_bfloat162& h, __nv_bfloat162& l) {
    h.x = __float2bfloat16(v0); l.x = __float2bfloat16(v0 - __bfloat162float(h.x));
    h.y = __float2bfloat16(v1); l.y = __float2bfloat16(v1 - __bfloat162float(h.y));
}

// =====================================================================
// PERSISTENT MEGA KERNEL: pass1 + Waa powers + boundary scan + pass3
// grid = 128 CTAs x 256 threads, 80KB dyn smem
// =====================================================================
__global__ __launch_bounds__(256, 1) void mega_k(
    const float* __restrict__ xp,
    __nv_bfloat16* p1h, __nv_bfloat16* p1l, __nv_bfloat16* p2h, __nv_bfloat16* p2l,
    const __nv_bfloat16* wah, const __nv_bfloat16* wal,
    const __nv_bfloat16* wth, const __nv_bfloat16* wtl,
    float* s1, float* bd, float* pA, float* pB, float* part,
    __nv_bfloat16* ah, __nv_bfloat16* al)
{
    extern __shared__ char smem[];
    const uint32_t sbase = smem_u32(smem);
    const int tid = threadIdx.x, lane = tid & 31, w = tid >> 5;
    const int wm = w & 1, wn = w >> 1;
    const int bid = blockIdx.x;
    const int row0 = (bid >> 3) * 128;   // M=2048 -> 16 blocks
    const int col0 = (bid & 7) * 128;    // N=1024 -> 8 blocks

    // ================= init1: p1 <- split(Xp[t=blk*16]) =================
    {
        const size_t base = (size_t)bid * 16384;
#pragma unroll
        for (int i = 0; i < 16; i++) {
            const size_t e = base + (size_t)(tid + i * 256) * 4;
            const int r = (int)(e >> 10), n = (int)(e & 1023);
            const int bb = r >> 5, blk = r & 31;
            float4 v = *(const float4*)&xp[((size_t)bb * CT + blk * S_) * CN + n];
            __nv_bfloat162 h0, h1, l0, l1;
            split2(v.x, v.y, h0, l0); split2(v.z, v.w, h1, l1);
            *(__nv_bfloat162*)&p1h[e] = h0; *(__nv_bfloat162*)&p1h[e + 2] = h1;
            *(__nv_bfloat162*)&p1l[e] = l0; *(__nv_bfloat162*)&p1l[e + 2] = l1;
        }
    }
    grid_sync();

    // ================= pass1: j = 1..15 =================
    for (int j = 1; j < S_; j++) {
        const bool in1 = (j & 1);
        const __nv_bfloat16* ih = in1 ? p1h : p2h;
        const __nv_bfloat16* il = in1 ? p1l : p2l;
        __nv_bfloat16* oh = in1 ? p2h : p1h;
        __nv_bfloat16* ol = in1 ? p2l : p1l;
        float acc[4][4][4];
        gemm_core(sbase, tid, wm, wn, lane, ih, il, wah, wal, row0, col0, acc);
        step_epi(acc, row0, col0, wm, wn, lane, xp, j,
                 (j == S_ - 1) ? s1 : nullptr, oh, ol, nullptr, nullptr);
        grid_sync();
    }

    // ================= powers: R16T = (Waa^16)^T via 4 TN-MMA levels =================
    // level l: G = A @ W^T where A = R_{2^l}T planes, W = R_{2^l} planes
    {
        const int prow0 = (bid >> 3) * 128;   // reuse 16x8 mapping; only bid<64 works
        const int pcol0 = (bid & 7) * 128;
        for (int lvl = 0; lvl < 4; lvl++) {
            const __nv_bfloat16 *iah, *ial, *ibh, *ibl;
            float* G = (lvl & 1) ? pB : pA;   // L0->pA, L1->pB, L2->pA, L3->pB
            if (lvl == 0) { iah = wth; ial = wtl; ibh = wah; ibl = wal; }
            else          { iah = p1h; ial = p1l; ibh = p2h; ibl = p2l; }
            if (bid < 64) {
                float acc[4][4][4];
                gemm_core(sbase, tid, wm, wn, lane, iah, ial, ibh, ibl,
                          (bid >> 3) * 128, (bid & 7) * 128, acc);
                // fp32 store epilogue
#pragma unroll
                for (int mi = 0; mi < 4; mi++) {
                    const int rb = (bid >> 3) * 128 + wm * 64 + mi * 16 + (lane >> 2);
#pragma unroll
                    for (int half = 0; half < 2; half++) {
                        const int m = rb + half * 8;
#pragma unroll
                        for (int ni = 0; ni < 4; ni++) {
                            const int c = (bid & 7) * 128 + wn * 32 + ni * 8 + (lane & 3) * 2;
                            *(float2*)&G[(size_t)m * CN + c] =
                                make_float2(acc[mi][ni][half * 2 + 0], acc[mi][ni][half * 2 + 1]);
                        }
                    }
                }
            }
            grid_sync();
            if (lvl < 3) {
                // SP: split(G) -> p1 planes;  split(G^T) -> p2 planes
                float (*ts)[33] = (float(*)[33])smem;
                for (int t8 = 0; t8 < 8; t8++) {
                    const int tile = bid * 8 + t8;
                    const int tr = tile >> 5, tc = tile & 31;
                    const int x = tid & 31, y8 = tid >> 5;  // 32 x 8
                    __syncthreads();
#pragma unroll
                    for (int p = 0; p < 4; p++) {
                        const int y = y8 + p * 8;
                        float v = G[(size_t)(tr * 32 + y) * CN + tc * 32 + x];
                        ts[y][x] = v;
                        __nv_bfloat16 h = __float2bfloat16(v);
                        const size_t di = (size_t)(tr * 32 + y) * CN + tc * 32 + x;
                        p1h[di] = h;
                        p1l[di] = __float2bfloat16(v - __bfloat162float(h));
                    }
                    __syncthreads();
#pragma unroll
                    for (int p = 0; p < 4; p++) {
                        const int y = y8 + p * 8;
                        float v = ts[x][y];
                        __nv_bfloat16 h = __float2bfloat16(v);
                        const size_t di = (size_t)(tc * 32 + y) * CN + tr * 32 + x;
                        p2h[di] = h;
                        p2l[di] = __float2bfloat16(v - __bfloat162float(h));
                    }
                }
                grid_sync();
            }
        }
    }
    // pB now holds R16T = (Waa^16)^T  fp32, [k][n] row-major

    // ================= boundary: b_0 = e_0; b_k = e_k + b_{k-1} @ R16T (NN) =================
    {
        // b_0 init
        {
            const size_t e = (size_t)bid * 512 + tid * 2;
            const int m = (int)(e >> 10), n = (int)(e & 1023);
            *(float2*)&bd[e] = *(const float2*)&s1[((size_t)(m * NBLK + 0)) * CN + n];
        }
        grid_sync();

        const int nb = bid & 15, kb = bid >> 4;     // 16 n-blocks(64) x 8 k-blocks(128)
        float (*Ps)[69] = (float(*)[69])smem;                       // [128k][64n]
        float (*Bs)[69] = (float(*)[69])(smem + 128 * 69 * 4);      // [128k][64m]
        // load loop-invariant R16T slice once
        for (int i = 0; i < 32; i++) {
            const int e = tid + i * 256;            // 8192
            const int kk = e >> 6, n = e & 63;
            Ps[kk][n] = pB[(size_t)(kb * 128 + kk) * CN + nb * 64 + n];
        }
        const int tm = tid & 15, tn = tid >> 4;
        for (int k = 1; k < NBLK; k++) {
            // load b_{k-1} chunk [64m][128k] transposed into Bs[k][m]
            const float* bsrc = bd + (size_t)(k - 1) * CB * CN;
            for (int i = 0; i < 32; i++) {
                const int e = tid + i * 256;
                const int m = e >> 7, kk = e & 127;
                Bs[kk][m] = bsrc[(size_t)m * CN + kb * 128 + kk];
            }
            __syncthreads();
            float acc[4][4];
#pragma unroll
            for (int i = 0; i < 4; i++)
#pragma unroll
                for (int j = 0; j < 4; j++) acc[i][j] = 0.f;
            for (int kk = 0; kk < 128; kk++) {
                float a0 = Bs[kk][tm * 4 + 0], a1 = Bs[kk][tm * 4 + 1];
                float a2 = Bs[kk][tm * 4 + 2], a3 = Bs[kk][tm * 4 + 3];
                float w0 = Ps[kk][tn * 4 + 0], w1 = Ps[kk][tn * 4 + 1];
                float w2 = Ps[kk][tn * 4 + 2], w3 = Ps[kk][tn * 4 + 3];
                acc[0][0] += a0 * w0; acc[0][1] += a0 * w1; acc[0][2] += a0 * w2; acc[0][3] += a0 * w3;
                acc[1][0] += a1 * w0; acc[1][1] += a1 * w1; acc[1][2] += a1 * w2; acc[1][3] += a1 * w3;
                acc[2][0] += a2 * w0; acc[2][1] += a2 * w1; acc[2][2] += a2 * w2; acc[2][3] += a2 * w3;
                acc[3][0] += a3 * w0; acc[3][1] += a3 * w1; acc[3][2] += a3 * w2; acc[3][3] += a3 * w3;
            }
            float* dst = part + (size_t)kb * CB * CN;
#pragma unroll
            for (int i = 0; i < 4; i++) {
                const int m = tm * 4 + i;
                *(float4*)&dst[(size_t)m * CN + nb * 64 + tn * 4] =
                    make_float4(acc[i][0], acc[i][1], acc[i][2], acc[i][3]);
            }
            grid_sync();
            // reduce: b_k = e_k + sum_s part[s]
            {
                const size_t e = (size_t)bid * 512 + tid * 2;
                const int m = (int)(e >> 10), n = (int)(e & 1023);
                float2 v = *(const float2*)&s1[((size_t)(m * NBLK + k)) * CN + n];
#pragma unroll
                for (int s = 0; s < 8; s++) {
                    float2 p = *(const float2*)&part[(size_t)s * CB * CN + e];
                    v.x += p.x; v.y += p.y;
                }
                *(float2*)&bd[(size_t)k * CB * CN + e] = v;
            }
            grid_sync();
        }
    }

    // ================= init3: p1 <- split(seed) =================
    {
        const size_t base = (size_t)bid * 16384;
#pragma unroll
        for (int i = 0; i < 16; i++) {
            const size_t e = base + (size_t)(tid + i * 256) * 4;
            const int r = (int)(e >> 10), n = (int)(e & 1023);
            const int bb = r >> 5, blk = r & 31;
            float4 v = make_float4(0.f, 0.f, 0.f, 0.f);
            if (blk) v = *(const float4*)&bd[((size_t)(blk - 1) * CB + bb) * CN + n];
            __nv_bfloat162 h0, h1, l0, l1;
            split2(v.x, v.y, h0, l0); split2(v.z, v.w, h1, l1);
            *(__nv_bfloat162*)&p1h[e] = h0; *(__nv_bfloat162*)&p1h[e + 2] = h1;
            *(__nv_bfloat162*)&p1l[e] = l0; *(__nv_bfloat162*)&p1l[e + 2] = l1;
        }
    }
    grid_sync();

    // ================= pass3: j = 0..15, write A planes =================
    for (int j = 0; j < S_; j++) {
        const bool in1 = ((j & 1) == 0);
        const __nv_bfloat16* ih = in1 ? p1h : p2h;
        const __nv_bfloat16* il = in1 ? p1l : p2l;
        __nv_bfloat16* oh = in1 ? p2h : p1h;
        __nv_bfloat16* ol = in1 ? p2l : p1l;
        float acc[4][4][4];
        gemm_core(sbase, tid, wm, wn, lane, ih, il, wah, wal, row0, col0, acc);
        step_epi(acc, row0, col0, wm, wn, lane, xp, j, nullptr, oh, ol, ah, al);
        if (j < S_ - 1) grid_sync();
    }
}

// =====================================================================
// Standalone big GEMM (phase A / Y): C = A@W^T + bias, fp32 out
// =====================================================================
__global__ __launch_bounds__(256) void mma_gemm_bias(
    const __nv_bfloat16* __restrict__ Ah, const __nv_bfloat16* __restrict__ Al,
    const __nv_bfloat16* __restrict__ Bh, const __nv_bfloat16* __restrict__ Bl,
    const float* __restrict__ bias, float* __restrict__ out)
{
    extern __shared__ char smem[];
    const uint32_t sbase = smem_u32(smem);
    const int tid = threadIdx.x, lane = tid & 31, w = tid >> 5;
    const int wm = w & 1, wn = w >> 1;
    const int row0 = blockIdx.y * 128, col0 = blockIdx.x * 128;
    float acc[4][4][4];
    gemm_core(sbase, tid, wm, wn, lane, Ah, Al, Bh, Bl, row0, col0, acc);
#pragma unroll
    for (int mi = 0; mi < 4; mi++) {
        const int rbase = row0 + wm * 64 + mi * 16 + (lane >> 2);
#pragma unroll
        for (int half = 0; half < 2; half++) {
            const int m = rbase + half * 8;
#pragma unroll
            for (int ni = 0; ni < 4; ni++) {
                const int c = col0 + wn * 32 + ni * 8 + (lane & 3) * 2;
                float v0 = acc[mi][ni][half * 2 + 0] + bias[c];
                float v1 = acc[mi][ni][half * 2 + 1] + bias[c + 1];
                *(float2*)&out[(size_t)m * CN + c] = make_float2(v0, v1);
            }
        }
    }
}

// ---------------- prep kernels ----------------
__global__ __launch_bounds__(256) void split_k(
    const float* __restrict__ src, __nv_bfloat16* __restrict__ hi, __nv_bfloat16* __restrict__ lo)
{
    const size_t e = ((size_t)blockIdx.x * 256 + threadIdx.x) * 4;
    float4 v = *(const float4*)&src[e];
    __nv_bfloat162 h0, h1, l0, l1;
    split2(v.x, v.y, h0, l0); split2(v.z, v.w, h1, l1);
    *(__nv_bfloat162*)&hi[e] = h0; *(__nv_bfloat162*)&hi[e + 2] = h1;
    *(__nv_bfloat162*)&lo[e] = l0; *(__nv_bfloat162*)&lo[e + 2] = l1;
}

// split of src^T (1024x1024)
__global__ __launch_bounds__(256) void tsplit_k(
    const float* __restrict__ src, __nv_bfloat16* __restrict__ hi, __nv_bfloat16* __restrict__ lo)
{
    __shared__ float ts[32][33];
    const int x = threadIdx.x & 31, y8 = threadIdx.x >> 5;
    const int tr = blockIdx.y, tc = blockIdx.x;
#pragma unroll
    for (int p = 0; p < 4; p++) {
        const int y = y8 + p * 8;
        ts[y][x] = src[(size_t)(tr * 32 + y) * CN + tc * 32 + x];
    }
    __syncthreads();
#pragma unroll
    for (int p = 0; p < 4; p++) {
        const int y = y8 + p * 8;
        float v = ts[x][y];
        __nv_bfloat16 h = __float2bfloat16(v);
        const size_t di = (size_t)(tc * 32 + y) * CN + tr * 32 + x;
        hi[di] = h;
        lo[di] = __float2bfloat16(v - __bfloat162float(h));
    }
}

// =====================================================================
// host
// =====================================================================
extern "C" void kernel_launch(void* const* d_in, const int* in_sizes, int n_in,
                              void* d_out, int out_size)
{
    const float* X   = (const float*)d_in[0];
    const float* Wax = (const float*)d_in[1];
    const float* Waa = (const float*)d_in[2];
    const float* ba  = (const float*)d_in[3];
    const float* Wy  = (const float*)d_in[4];
    const float* by  = (const float*)d_in[5];
    float* Y = (float*)d_out;

    void *xpv, *xchv, *xclv, *ahv, *alv, *s1v, *p1hv, *p1lv, *p2hv, *p2lv;
    void *wxhv, *wxlv, *wahv, *walv, *wyhv, *wylv, *wthv, *wtlv;
    void *bdv, *pAv, *pBv, *partv;
    cudaGetSymbolAddress(&xpv, g_xp);   cudaGetSymbolAddress(&xchv, g_xch);
    cudaGetSymbolAddress(&xclv, g_xcl); cudaGetSymbolAddress(&ahv, g_ah);
    cudaGetSymbolAddress(&alv, g_al);   cudaGetSymbolAddress(&s1v, g_s1);
    cudaGetSymbolAddress(&p1hv, g_p1h); cudaGetSymbolAddress(&p1lv, g_p1l);
    cudaGetSymbolAddress(&p2hv, g_p2h); cudaGetSymbolAddress(&p2lv, g_p2l);
    cudaGetSymbolAddress(&wxhv, g_wxh); cudaGetSymbolAddress(&wxlv, g_wxl);
    cudaGetSymbolAddress(&wahv, g_wah); cudaGetSymbolAddress(&walv, g_wal);
    cudaGetSymbolAddress(&wyhv, g_wyh); cudaGetSymbolAddress(&wylv, g_wyl);
    cudaGetSymbolAddress(&wthv, g_wth); cudaGetSymbolAddress(&wtlv, g_wtl);
    cudaGetSymbolAddress(&bdv, g_bd);   cudaGetSymbolAddress(&pAv, g_pA);
    cudaGetSymbolAddress(&pBv, g_pB);   cudaGetSymbolAddress(&partv, g_part);

    float* xp = (float*)xpv; float* s1 = (float*)s1v;
    float* bd = (float*)bdv; float* pA = (float*)pAv; float* pB = (float*)pBv;
    float* part = (float*)partv;
    __nv_bfloat16* xch = (__nv_bfloat16*)xchv; __nv_bfloat16* xcl = (__nv_bfloat16*)xclv;
    __nv_bfloat16* ah  = (__nv_bfloat16*)ahv;  __nv_bfloat16* al  = (__nv_bfloat16*)alv;
    __nv_bfloat16* p1h = (__nv_bfloat16*)p1hv; __nv_bfloat16* p1l = (__nv_bfloat16*)p1lv;
    __nv_bfloat16* p2h = (__nv_bfloat16*)p2hv; __nv_bfloat16* p2l = (__nv_bfloat16*)p2lv;
    __nv_bfloat16* wxh = (__nv_bfloat16*)wxhv; __nv_bfloat16* wxl = (__nv_bfloat16*)wxlv;
    __nv_bfloat16* wah = (__nv_bfloat16*)wahv; __nv_bfloat16* wal = (__nv_bfloat16*)walv;
    __nv_bfloat16* wyh = (__nv_bfloat16*)wyhv; __nv_bfloat16* wyl = (__nv_bfloat16*)wylv;
    __nv_bfloat16* wth = (__nv_bfloat16*)wthv; __nv_bfloat16* wtl = (__nv_bfloat16*)wtlv;

    cudaFuncSetAttribute(mma_gemm_bias, cudaFuncAttributeMaxDynamicSharedMemorySize, SMEM_BYTES);
    cudaFuncSetAttribute(mega_k,        cudaFuncAttributeMaxDynamicSharedMemorySize, SMEM_BYTES);

    // ---- prep ----
    split_k<<<(MROWS * CN) / 1024, 256>>>(X, xch, xcl);
    split_k<<<(CN * CN) / 1024, 256>>>(Wax, wxh, wxl);
    split_k<<<(CN * CN) / 1024, 256>>>(Waa, wah, wal);
    split_k<<<(CN * CN) / 1024, 256>>>(Wy, wyh, wyl);
    tsplit_k<<<dim3(32, 32), 256>>>(Waa, wth, wtl);

    // ---- Phase A: Xp = X @ Wax^T + ba ----
    mma_gemm_bias<<<dim3(CN / 128, MROWS / 128), 256, SMEM_BYTES>>>(
        xch, xcl, wxh, wxl, ba, xp);

    // ---- persistent middle: pass1 + powers + boundary + pass3 ----
    mega_k<<<NCTA, 256, SMEM_BYTES>>>(
        xp, p1h, p1l, p2h, p2l, wah, wal, wth, wtl,
        s1, bd, pA, pB, part, ah, al);

    // ---- Phase Y: Y = A @ Wy^T + by ----
    mma_gemm_bias<<<dim3(CN / 128, MROWS / 128), 256, SMEM_BYTES>>>(
        ah, al, wyh, wyl, by, Y);
}

// round 5
// speedup vs baseline: 3.1777x; 1.4266x over previous
#include <cuda_runtime.h>
#include <cuda_fp16.h>
#include <cstdint>

// ---------------- problem constants ----------------
#define CB   64
#define CT   512
#define CD   1024
#define CN   1024
#define S_   16
#define NBLK 32
#define MROWS (CB * CT)    // 32768
#define MST   (CB * NBLK)  // 2048
#define NCTA  128          // persistent grid (one wave)

// ---------------- scratch ----------------
__device__ float   g_xp [(size_t)MROWS * CN];   // Xp fp32 (step addend)
__device__ __half  g_xh [(size_t)MROWS * CN];   // X hi plane (A-side)
__device__ __half  g_ah [(size_t)MROWS * CN];   // a_t hi plane (phase-Y A-side)
__device__ float   g_s1 [(size_t)MST * CN];     // E states fp32
__device__ __half  g_p1h[(size_t)MST * CN];     // state ping (hi only)
__device__ __half  g_p2h[(size_t)MST * CN];     // state pong (hi only)
__device__ __half  g_q2h[(size_t)CN * CN];      // powers B-side hi
__device__ __half  g_q2l[(size_t)CN * CN];      // powers B-side lo
__device__ __half  g_wxh[(size_t)CN * CN], g_wxl[(size_t)CN * CN];
__device__ __half  g_wah[(size_t)CN * CN], g_wal[(size_t)CN * CN];
__device__ __half  g_wyh[(size_t)CN * CN], g_wyl[(size_t)CN * CN];
__device__ __half  g_wth[(size_t)CN * CN];      // Waa^T hi (powers L0 A-side)
__device__ float g_bd[(size_t)NBLK * CB * CN];
__device__ float g_pA[(size_t)CN * CN];
__device__ float g_pB[(size_t)CN * CN];
__device__ float g_part[(size_t)8 * CB * CN];
__device__ unsigned g_cnt;
__device__ unsigned g_gen;

// =====================================================================
// Portable PTX helpers (sm_80-class only)
// =====================================================================
__device__ __forceinline__ uint32_t smem_u32(const void* p) {
    return (uint32_t)__cvta_generic_to_shared(p);
}
__device__ __forceinline__ void cp16(uint32_t dst, const void* src) {
    asm volatile("cp.async.cg.shared.global [%0], [%1], 16;\n" :: "r"(dst), "l"(src));
}
__device__ __forceinline__ void cp_commit() {
    asm volatile("cp.async.commit_group;\n" ::: "memory");
}
__device__ __forceinline__ void cp_wait0() {
    asm volatile("cp.async.wait_group 0;\n" ::: "memory");
}
__device__ __forceinline__ void ldsm4(uint32_t& r0, uint32_t& r1, uint32_t& r2, uint32_t& r3, uint32_t a) {
    asm volatile("ldmatrix.sync.aligned.m8n8.x4.shared.b16 {%0,%1,%2,%3}, [%4];\n"
                 : "=r"(r0), "=r"(r1), "=r"(r2), "=r"(r3) : "r"(a));
}
__device__ __forceinline__ void mma16816(float* d, const uint32_t* a, uint32_t b0, uint32_t b1) {
    asm volatile(
        "mma.sync.aligned.m16n8k16.row.col.f32.f16.f16.f32 "
        "{%0,%1,%2,%3}, {%4,%5,%6,%7}, {%8,%9}, {%0,%1,%2,%3};\n"
        : "+f"(d[0]), "+f"(d[1]), "+f"(d[2]), "+f"(d[3])
        : "r"(a[0]), "r"(a[1]), "r"(a[2]), "r"(a[3]), "r"(b0), "r"(b1));
}

// grid-wide barrier: sense-reversing, deterministic, replay-safe
__device__ __forceinline__ void grid_sync() {
    __syncthreads();
    if (threadIdx.x == 0) {
        __threadfence();
        volatile unsigned* gen = &g_gen;
        unsigned my = *gen;
        unsigned old = atomicAdd(&g_cnt, 1u);
        if (old == (unsigned)(NCTA - 1)) {
            g_cnt = 0u;
            __threadfence();
            *gen = my + 1u;
        } else {
            while (*gen == my) { }
        }
        __threadfence();
    }
    __syncthreads();
}

// smem tile: 128 rows x 32 fp16, padded to 40/row
#define TROW   40
#define TILE_B (128 * TROW * 2)   // 10240 bytes
#define STAGE_B (3 * TILE_B)      // Ah, Bh, Bl  (30720)
#define GEMM_SMEM (2 * STAGE_B)   // 61440
#define MEGA_SMEM 70656           // boundary chain needs 2*128*69*4

// ---------------- per-stage loads (3 tiles) ----------------
__device__ __forceinline__ void stage_load(
    uint32_t sbase, int buf,
    const __half* __restrict__ Ah,
    const __half* __restrict__ Bh, const __half* __restrict__ Bl,
    int row0, int col0, int k0, int tid)
{
    const __half* gp0 = Ah + (size_t)row0 * CN + k0;
    const __half* gp1 = Bh + (size_t)col0 * CN + k0;
    const __half* gp2 = Bl + (size_t)col0 * CN + k0;
    uint32_t base = sbase + buf * STAGE_B;
#pragma unroll
    for (int u = 0; u < 2; u++) {
        int e = tid + u * 256;
        int r = e >> 2, cu = e & 3;
        uint32_t off = (uint32_t)(r * (TROW * 2) + cu * 16);
        size_t gs = (size_t)r * CN + cu * 8;
        cp16(base + 0 * TILE_B + off, gp0 + gs);
        cp16(base + 1 * TILE_B + off, gp1 + gs);
        cp16(base + 2 * TILE_B + off, gp2 + gs);
    }
}

// ---------------- per-stage compute: 2-term fp16 MMA ----------------
__device__ __forceinline__ void stage_compute(
    uint32_t sbase, int buf, int wm, int wn, int lane, float acc[4][4][4])
{
    const uint32_t b0 = sbase + buf * STAGE_B;
    const uint32_t aH = b0, bH = b0 + TILE_B, bL = b0 + 2 * TILE_B;
    const int arow = wm * 64 + (lane & 15);
    const int brow = wn * 32 + (lane & 7) + ((lane >> 4) & 1) * 8;
#pragma unroll
    for (int k16 = 0; k16 < 2; k16++) {
        const int akc = k16 * 16 + (lane >> 4) * 8;
        const int bkc = k16 * 16 + ((lane >> 3) & 1) * 8;
        uint32_t af[4][4], bh[2][4], bl[2][4];
#pragma unroll
        for (int mi = 0; mi < 4; mi++)
            ldsm4(af[mi][0], af[mi][1], af[mi][2], af[mi][3],
                  aH + (uint32_t)((arow + mi * 16) * (TROW * 2) + akc * 2));
#pragma unroll
        for (int nf = 0; nf < 2; nf++)
            ldsm4(bh[nf][0], bh[nf][1], bh[nf][2], bh[nf][3],
                  bH + (uint32_t)((brow + nf * 16) * (TROW * 2) + bkc * 2));
#pragma unroll
        for (int nf = 0; nf < 2; nf++)
            ldsm4(bl[nf][0], bl[nf][1], bl[nf][2], bl[nf][3],
                  bL + (uint32_t)((brow + nf * 16) * (TROW * 2) + bkc * 2));
#pragma unroll
        for (int mi = 0; mi < 4; mi++)
#pragma unroll
            for (int nf = 0; nf < 2; nf++)
#pragma unroll
                for (int sub = 0; sub < 2; sub++) {
                    mma16816(acc[mi][nf * 2 + sub], af[mi], bh[nf][sub * 2], bh[nf][sub * 2 + 1]);
                    mma16816(acc[mi][nf * 2 + sub], af[mi], bl[nf][sub * 2], bl[nf][sub * 2 + 1]);
                }
    }
}

// ---------------- full K=1024 pipelined GEMM core ----------------
__device__ __forceinline__ void gemm_core(
    uint32_t sbase, int tid, int wm, int wn, int lane,
    const __half* Ah, const __half* Bh, const __half* Bl,
    int row0, int col0, float acc[4][4][4])
{
#pragma unroll
    for (int i = 0; i < 4; i++)
#pragma unroll
        for (int j = 0; j < 4; j++)
#pragma unroll
            for (int r = 0; r < 4; r++) acc[i][j][r] = 0.f;
    stage_load(sbase, 0, Ah, Bh, Bl, row0, col0, 0, tid);
    cp_commit();
    const int NS = CN / 32;
    for (int s = 0; s < NS; s++) {
        cp_wait0();
        __syncthreads();
        if (s + 1 < NS) {
            stage_load(sbase, (s + 1) & 1, Ah, Bh, Bl, row0, col0, (s + 1) * 32, tid);
            cp_commit();
        }
        stage_compute(sbase, s & 1, wm, wn, lane, acc);
        __syncthreads();
    }
}

// ---------------- step epilogue ----------------
__device__ __forceinline__ void step_epi(
    float acc[4][4][4], int row0, int col0, int wm, int wn, int lane,
    const float* __restrict__ xp, int jstep,
    float* __restrict__ f32out,
    __half* __restrict__ sh, __half* __restrict__ oah)
{
#pragma unroll
    for (int mi = 0; mi < 4; mi++) {
        const int rbase = row0 + wm * 64 + mi * 16 + (lane >> 2);
#pragma unroll
        for (int half = 0; half < 2; half++) {
            const int m = rbase + half * 8;
            const int bb = m >> 5, blk = m & 31;
            const size_t xoff = ((size_t)bb * CT + blk * S_ + jstep) * CN;
#pragma unroll
            for (int ni = 0; ni < 4; ni++) {
                const int c = col0 + wn * 32 + ni * 8 + (lane & 3) * 2;
                float2 x = *(const float2*)&xp[xoff + c];
                float v0 = acc[mi][ni][half * 2 + 0] + x.x;
                float v1 = acc[mi][ni][half * 2 + 1] + x.y;
                if (f32out)
                    *(float2*)&f32out[(size_t)m * CN + c] = make_float2(v0, v1);
                __half2 h = __floats2half2_rn(v0, v1);
                *(__half2*)&sh[(size_t)m * CN + c] = h;
                if (oah)
                    *(__half2*)&oah[xoff + c] = h;
            }
        }
    }
}

// =====================================================================
// PERSISTENT MEGA KERNEL
// =====================================================================
__global__ __launch_bounds__(256, 1) void mega_k(
    const float* __restrict__ xp,
    __half* p1h, __half* p2h, __half* q2h, __half* q2l,
    const __half* wah, const __half* wal, const __half* wth,
    float* s1, float* bd, float* pA, float* pB, float* part,
    __half* ah)
{
    extern __shared__ char smem[];
    const uint32_t sbase = smem_u32(smem);
    const int tid = threadIdx.x, lane = tid & 31, w = tid >> 5;
    const int wm = w & 1, wn = w >> 1;
    const int bid = blockIdx.x;
    const int row0 = (bid >> 3) * 128;
    const int col0 = (bid & 7) * 128;

    // ===== init1: p1h <- fp16(Xp[t=blk*16]) =====
    {
        const size_t base = (size_t)bid * 16384;
#pragma unroll
        for (int i = 0; i < 16; i++) {
            const size_t e = base + (size_t)(tid + i * 256) * 4;
            const int r = (int)(e >> 10), n = (int)(e & 1023);
            const int bb = r >> 5, blk = r & 31;
            float4 v = *(const float4*)&xp[((size_t)bb * CT + blk * S_) * CN + n];
            *(__half2*)&p1h[e]     = __floats2half2_rn(v.x, v.y);
            *(__half2*)&p1h[e + 2] = __floats2half2_rn(v.z, v.w);
        }
    }
    grid_sync();

    // ===== pass1: j = 1..15 =====
    for (int j = 1; j < S_; j++) {
        const bool in1 = (j & 1);
        const __half* ih = in1 ? p1h : p2h;
        __half* oh = in1 ? p2h : p1h;
        float acc[4][4][4];
        gemm_core(sbase, tid, wm, wn, lane, ih, wah, wal, row0, col0, acc);
        step_epi(acc, row0, col0, wm, wn, lane, xp, j,
                 (j == S_ - 1) ? s1 : nullptr, oh, nullptr);
        grid_sync();
    }

    // ===== powers: R16T = (Waa^16)^T via 4 levels =====
    {
        for (int lvl = 0; lvl < 4; lvl++) {
            const __half *iah, *ibh, *ibl;
            float* G = (lvl & 1) ? pB : pA;
            if (lvl == 0) { iah = wth; ibh = wah; ibl = wal; }
            else          { iah = p1h; ibh = q2h; ibl = q2l; }
            if (bid < 64) {
                float acc[4][4][4];
                gemm_core(sbase, tid, wm, wn, lane, iah, ibh, ibl,
                          (bid >> 3) * 128, (bid & 7) * 128, acc);
#pragma unroll
                for (int mi = 0; mi < 4; mi++) {
                    const int rb = (bid >> 3) * 128 + wm * 64 + mi * 16 + (lane >> 2);
#pragma unroll
                    for (int half = 0; half < 2; half++) {
                        const int m = rb + half * 8;
#pragma unroll
                        for (int ni = 0; ni < 4; ni++) {
                            const int c = (bid & 7) * 128 + wn * 32 + ni * 8 + (lane & 3) * 2;
                            *(float2*)&G[(size_t)m * CN + c] =
                                make_float2(acc[mi][ni][half * 2 + 0], acc[mi][ni][half * 2 + 1]);
                        }
                    }
                }
            }
            grid_sync();
            if (lvl < 3) {
                // split(G) -> p1h (A-side);  split(G^T) -> q2h/q2l (B-side)
                float (*ts)[33] = (float(*)[33])smem;
                for (int t8 = 0; t8 < 8; t8++) {
                    const int tile = bid * 8 + t8;
                    const int tr = tile >> 5, tc = tile & 31;
                    const int x = tid & 31, y8 = tid >> 5;
                    __syncthreads();
#pragma unroll
                    for (int p = 0; p < 4; p++) {
                        const int y = y8 + p * 8;
                        float v = G[(size_t)(tr * 32 + y) * CN + tc * 32 + x];
                        ts[y][x] = v;
                        p1h[(size_t)(tr * 32 + y) * CN + tc * 32 + x] = __float2half_rn(v);
                    }
                    __syncthreads();
#pragma unroll
                    for (int p = 0; p < 4; p++) {
                        const int y = y8 + p * 8;
                        float v = ts[x][y];
                        __half h = __float2half_rn(v);
                        const size_t di = (size_t)(tc * 32 + y) * CN + tr * 32 + x;
                        q2h[di] = h;
                        q2l[di] = __float2half_rn(v - __half2float(h));
                    }
                }
                grid_sync();
            }
        }
    }
    // pB holds R16T = (Waa^16)^T fp32

    // ===== boundary chain (fp32) =====
    {
        {
            const size_t e = (size_t)bid * 512 + tid * 2;
            const int m = (int)(e >> 10), n = (int)(e & 1023);
            *(float2*)&bd[e] = *(const float2*)&s1[((size_t)(m * NBLK + 0)) * CN + n];
        }
        grid_sync();

        const int nb = bid & 15, kb = bid >> 4;
        float (*Ps)[69] = (float(*)[69])smem;
        float (*Bs)[69] = (float(*)[69])(smem + 128 * 69 * 4);
        for (int i = 0; i < 32; i++) {
            const int e = tid + i * 256;
            const int kk = e >> 6, n = e & 63;
            Ps[kk][n] = pB[(size_t)(kb * 128 + kk) * CN + nb * 64 + n];
        }
        const int tm = tid & 15, tn = tid >> 4;
        for (int k = 1; k < NBLK; k++) {
            const float* bsrc = bd + (size_t)(k - 1) * CB * CN;
            for (int i = 0; i < 32; i++) {
                const int e = tid + i * 256;
                const int m = e >> 7, kk = e & 127;
                Bs[kk][m] = bsrc[(size_t)m * CN + kb * 128 + kk];
            }
            __syncthreads();
            float acc[4][4];
#pragma unroll
            for (int i = 0; i < 4; i++)
#pragma unroll
                for (int j = 0; j < 4; j++) acc[i][j] = 0.f;
            for (int kk = 0; kk < 128; kk++) {
                float a0 = Bs[kk][tm * 4 + 0], a1 = Bs[kk][tm * 4 + 1];
                float a2 = Bs[kk][tm * 4 + 2], a3 = Bs[kk][tm * 4 + 3];
                float w0 = Ps[kk][tn * 4 + 0], w1 = Ps[kk][tn * 4 + 1];
                float w2 = Ps[kk][tn * 4 + 2], w3 = Ps[kk][tn * 4 + 3];
                acc[0][0] += a0 * w0; acc[0][1] += a0 * w1; acc[0][2] += a0 * w2; acc[0][3] += a0 * w3;
                acc[1][0] += a1 * w0; acc[1][1] += a1 * w1; acc[1][2] += a1 * w2; acc[1][3] += a1 * w3;
                acc[2][0] += a2 * w0; acc[2][1] += a2 * w1; acc[2][2] += a2 * w2; acc[2][3] += a2 * w3;
                acc[3][0] += a3 * w0; acc[3][1] += a3 * w1; acc[3][2] += a3 * w2; acc[3][3] += a3 * w3;
            }
            float* dst = part + (size_t)kb * CB * CN;
#pragma unroll
            for (int i = 0; i < 4; i++) {
                const int m = tm * 4 + i;
                *(float4*)&dst[(size_t)m * CN + nb * 64 + tn * 4] =
                    make_float4(acc[i][0], acc[i][1], acc[i][2], acc[i][3]);
            }
            grid_sync();
            {
                const size_t e = (size_t)bid * 512 + tid * 2;
                const int m = (int)(e >> 10), n = (int)(e & 1023);
                float2 v = *(const float2*)&s1[((size_t)(m * NBLK + k)) * CN + n];
#pragma unroll
                for (int s = 0; s < 8; s++) {
                    float2 p = *(const float2*)&part[(size_t)s * CB * CN + e];
                    v.x += p.x; v.y += p.y;
                }
                *(float2*)&bd[(size_t)k * CB * CN + e] = v;
            }
            grid_sync();
        }
    }

    // ===== init3: p1h <- fp16(seed) =====
    {
        const size_t base = (size_t)bid * 16384;
#pragma unroll
        for (int i = 0; i < 16; i++) {
            const size_t e = base + (size_t)(tid + i * 256) * 4;
            const int r = (int)(e >> 10), n = (int)(e & 1023);
            const int bb = r >> 5, blk = r & 31;
            float4 v = make_float4(0.f, 0.f, 0.f, 0.f);
            if (blk) v = *(const float4*)&bd[((size_t)(blk - 1) * CB + bb) * CN + n];
            *(__half2*)&p1h[e]     = __floats2half2_rn(v.x, v.y);
            *(__half2*)&p1h[e + 2] = __floats2half2_rn(v.z, v.w);
        }
    }
    grid_sync();

    // ===== pass3: j = 0..15 =====
    for (int j = 0; j < S_; j++) {
        const bool in1 = ((j & 1) == 0);
        const __half* ih = in1 ? p1h : p2h;
        __half* oh = in1 ? p2h : p1h;
        float acc[4][4][4];
        gemm_core(sbase, tid, wm, wn, lane, ih, wah, wal, row0, col0, acc);
        step_epi(acc, row0, col0, wm, wn, lane, xp, j, nullptr, oh, ah);
        if (j < S_ - 1) grid_sync();
    }
}

// =====================================================================
// Standalone big GEMM (phase A / Y): C = A@W^T + bias
// =====================================================================
__global__ __launch_bounds__(256, 2) void mma_gemm_bias(
    const __half* __restrict__ Ah,
    const __half* __restrict__ Bh, const __half* __restrict__ Bl,
    const float* __restrict__ bias, float* __restrict__ out)
{
    extern __shared__ char smem[];
    const uint32_t sbase = smem_u32(smem);
    const int tid = threadIdx.x, lane = tid & 31, w = tid >> 5;
    const int wm = w & 1, wn = w >> 1;
    const int row0 = blockIdx.y * 128, col0 = blockIdx.x * 128;
    float acc[4][4][4];
    gemm_core(sbase, tid, wm, wn, lane, Ah, Bh, Bl, row0, col0, acc);
#pragma unroll
    for (int mi = 0; mi < 4; mi++) {
        const int rbase = row0 + wm * 64 + mi * 16 + (lane >> 2);
#pragma unroll
        for (int half = 0; half < 2; half++) {
            const int m = rbase + half * 8;
#pragma unroll
            for (int ni = 0; ni < 4; ni++) {
                const int c = col0 + wn * 32 + ni * 8 + (lane & 3) * 2;
                float v0 = acc[mi][ni][half * 2 + 0] + bias[c];
                float v1 = acc[mi][ni][half * 2 + 1] + bias[c + 1];
                *(float2*)&out[(size_t)m * CN + c] = make_float2(v0, v1);
            }
        }
    }
}

// ---------------- prep kernels ----------------
// hi-only split (activations / X)
__global__ __launch_bounds__(256) void hsplit_k(
    const float* __restrict__ src, __half* __restrict__ hi)
{
    const size_t e = ((size_t)blockIdx.x * 256 + threadIdx.x) * 4;
    float4 v = *(const float4*)&src[e];
    *(__half2*)&hi[e]     = __floats2half2_rn(v.x, v.y);
    *(__half2*)&hi[e + 2] = __floats2half2_rn(v.z, v.w);
}

// hi+lo split (weights)
__global__ __launch_bounds__(256) void wsplit_k(
    const float* __restrict__ src, __half* __restrict__ hi, __half* __restrict__ lo)
{
    const size_t e = ((size_t)blockIdx.x * 256 + threadIdx.x) * 4;
    float4 v = *(const float4*)&src[e];
    __half h0 = __float2half_rn(v.x), h1 = __float2half_rn(v.y);
    __half h2 = __float2half_rn(v.z), h3 = __float2half_rn(v.w);
    hi[e] = h0; hi[e + 1] = h1; hi[e + 2] = h2; hi[e + 3] = h3;
    lo[e]     = __float2half_rn(v.x - __half2float(h0));
    lo[e + 1] = __float2half_rn(v.y - __half2float(h1));
    lo[e + 2] = __float2half_rn(v.z - __half2float(h2));
    lo[e + 3] = __float2half_rn(v.w - __half2float(h3));
}

// hi-only split of src^T
__global__ __launch_bounds__(256) void tsplit_k(
    const float* __restrict__ src, __half* __restrict__ hi)
{
    __shared__ float ts[32][33];
    const int x = threadIdx.x & 31, y8 = threadIdx.x >> 5;
    const int tr = blockIdx.y, tc = blockIdx.x;
#pragma unroll
    for (int p = 0; p < 4; p++) {
        const int y = y8 + p * 8;
        ts[y][x] = src[(size_t)(tr * 32 + y) * CN + tc * 32 + x];
    }
    __syncthreads();
#pragma unroll
    for (int p = 0; p < 4; p++) {
        const int y = y8 + p * 8;
        hi[(size_t)(tc * 32 + y) * CN + tr * 32 + x] = __float2half_rn(ts[x][y]);
    }
}

// =====================================================================
// host
// =====================================================================
extern "C" void kernel_launch(void* const* d_in, const int* in_sizes, int n_in,
                              void* d_out, int out_size)
{
    const float* X   = (const float*)d_in[0];
    const float* Wax = (const float*)d_in[1];
    const float* Waa = (const float*)d_in[2];
    const float* ba  = (const float*)d_in[3];
    const float* Wy  = (const float*)d_in[4];
    const float* by  = (const float*)d_in[5];
    float* Y = (float*)d_out;

    void *xpv, *xhv, *ahv, *s1v, *p1hv, *p2hv, *q2hv, *q2lv;
    void *wxhv, *wxlv, *wahv, *walv, *wyhv, *wylv, *wthv;
    void *bdv, *pAv, *pBv, *partv;
    cudaGetSymbolAddress(&xpv, g_xp);   cudaGetSymbolAddress(&xhv, g_xh);
    cudaGetSymbolAddress(&ahv, g_ah);   cudaGetSymbolAddress(&s1v, g_s1);
    cudaGetSymbolAddress(&p1hv, g_p1h); cudaGetSymbolAddress(&p2hv, g_p2h);
    cudaGetSymbolAddress(&q2hv, g_q2h); cudaGetSymbolAddress(&q2lv, g_q2l);
    cudaGetSymbolAddress(&wxhv, g_wxh); cudaGetSymbolAddress(&wxlv, g_wxl);
    cudaGetSymbolAddress(&wahv, g_wah); cudaGetSymbolAddress(&walv, g_wal);
    cudaGetSymbolAddress(&wyhv, g_wyh); cudaGetSymbolAddress(&wylv, g_wyl);
    cudaGetSymbolAddress(&wthv, g_wth);
    cudaGetSymbolAddress(&bdv, g_bd);   cudaGetSymbolAddress(&pAv, g_pA);
    cudaGetSymbolAddress(&pBv, g_pB);   cudaGetSymbolAddress(&partv, g_part);

    float* xp = (float*)xpv; float* s1 = (float*)s1v;
    float* bd = (float*)bdv; float* pA = (float*)pAv; float* pB = (float*)pBv;
    float* part = (float*)partv;
    __half* xh  = (__half*)xhv;  __half* ah  = (__half*)ahv;
    __half* p1h = (__half*)p1hv; __half* p2h = (__half*)p2hv;
    __half* q2h = (__half*)q2hv; __half* q2l = (__half*)q2lv;
    __half* wxh = (__half*)wxhv; __half* wxl = (__half*)wxlv;
    __half* wah = (__half*)wahv; __half* wal = (__half*)walv;
    __half* wyh = (__half*)wyhv; __half* wyl = (__half*)wylv;
    __half* wth = (__half*)wthv;

    cudaFuncSetAttribute(mma_gemm_bias, cudaFuncAttributeMaxDynamicSharedMemorySize, GEMM_SMEM);
    cudaFuncSetAttribute(mega_k,        cudaFuncAttributeMaxDynamicSharedMemorySize, MEGA_SMEM);

    // ---- prep ----
    hsplit_k<<<(MROWS * CN) / 1024, 256>>>(X, xh);
    wsplit_k<<<(CN * CN) / 1024, 256>>>(Wax, wxh, wxl);
    wsplit_k<<<(CN * CN) / 1024, 256>>>(Waa, wah, wal);
    wsplit_k<<<(CN * CN) / 1024, 256>>>(Wy, wyh, wyl);
    tsplit_k<<<dim3(32, 32), 256>>>(Waa, wth);

    // ---- Phase A: Xp = X @ Wax^T + ba ----
    mma_gemm_bias<<<dim3(CN / 128, MROWS / 128), 256, GEMM_SMEM>>>(
        xh, wxh, wxl, ba, xp);

    // ---- persistent middle ----
    mega_k<<<NCTA, 256, MEGA_SMEM>>>(
        xp, p1h, p2h, q2h, q2l, wah, wal, wth,
        s1, bd, pA, pB, part, ah);

    // ---- Phase Y: Y = A @ Wy^T + by ----
    mma_gemm_bias<<<dim3(CN / 128, MROWS / 128), 256, GEMM_SMEM>>>(
        ah, wyh, wyl, by, Y);
}

// round 6
// speedup vs baseline: 4.1688x; 1.3119x over previous
#include <cuda_runtime.h>
#include <cuda_fp16.h>
#include <cstdint>

// ---------------- problem constants ----------------
#define CB   64
#define CT   512
#define CD   1024
#define CN   1024
#define S_   16
#define NBLK 32
#define MROWS (CB * CT)    // 32768
#define MST   (CB * NBLK)  // 2048
#define NCTA  128          // persistent grid (one wave)

// ---------------- scratch ----------------
__device__ float   g_xp [(size_t)MROWS * CN];   // Xp fp32 (step addend)
__device__ __half  g_xh [(size_t)MROWS * CN];   // X hi plane
__device__ __half  g_ah [(size_t)MROWS * CN];   // a_t hi plane (phase-Y A-side)
__device__ float   g_s1 [(size_t)MST * CN];     // E states fp32
__device__ __half  g_p1h[(size_t)MST * CN];     // state ping
__device__ __half  g_p2h[(size_t)MST * CN];     // state pong
__device__ __half  g_q2h[(size_t)CN * CN];      // powers B-side hi
__device__ __half  g_q2l[(size_t)CN * CN];      // powers B-side lo
__device__ __half  g_wxh[(size_t)CN * CN];
__device__ __half  g_wah[(size_t)CN * CN], g_wal[(size_t)CN * CN]; // Waa hi/lo (steps use hi; powers use both)
__device__ __half  g_wyh[(size_t)CN * CN];
__device__ __half  g_wth[(size_t)CN * CN];      // Waa^T hi (powers L0 A-side)
__device__ float g_bd[(size_t)NBLK * CB * CN];
__device__ float g_pA[(size_t)CN * CN];
__device__ float g_pB[(size_t)CN * CN];
__device__ float g_part[(size_t)8 * CB * CN];
__device__ unsigned g_cnt;
__device__ unsigned g_gen;

// =====================================================================
// Portable PTX helpers (sm_80-class only)
// =====================================================================
__device__ __forceinline__ uint32_t smem_u32(const void* p) {
    return (uint32_t)__cvta_generic_to_shared(p);
}
__device__ __forceinline__ void cp16(uint32_t dst, const void* src) {
    asm volatile("cp.async.cg.shared.global [%0], [%1], 16;\n" :: "r"(dst), "l"(src));
}
__device__ __forceinline__ void cp_commit() {
    asm volatile("cp.async.commit_group;\n" ::: "memory");
}
__device__ __forceinline__ void cp_wait0() {
    asm volatile("cp.async.wait_group 0;\n" ::: "memory");
}
__device__ __forceinline__ void ldsm4(uint32_t& r0, uint32_t& r1, uint32_t& r2, uint32_t& r3, uint32_t a) {
    asm volatile("ldmatrix.sync.aligned.m8n8.x4.shared.b16 {%0,%1,%2,%3}, [%4];\n"
                 : "=r"(r0), "=r"(r1), "=r"(r2), "=r"(r3) : "r"(a));
}
__device__ __forceinline__ void mma16816(float* d, const uint32_t* a, uint32_t b0, uint32_t b1) {
    asm volatile(
        "mma.sync.aligned.m16n8k16.row.col.f32.f16.f16.f32 "
        "{%0,%1,%2,%3}, {%4,%5,%6,%7}, {%8,%9}, {%0,%1,%2,%3};\n"
        : "+f"(d[0]), "+f"(d[1]), "+f"(d[2]), "+f"(d[3])
        : "r"(a[0]), "r"(a[1]), "r"(a[2]), "r"(a[3]), "r"(b0), "r"(b1));
}

// grid-wide barrier: sense-reversing, deterministic, replay-safe
__device__ __forceinline__ void grid_sync() {
    __syncthreads();
    if (threadIdx.x == 0) {
        __threadfence();
        volatile unsigned* gen = &g_gen;
        unsigned my = *gen;
        unsigned old = atomicAdd(&g_cnt, 1u);
        if (old == (unsigned)(NCTA - 1)) {
            g_cnt = 0u;
            __threadfence();
            *gen = my + 1u;
        } else {
            while (*gen == my) { }
        }
        __threadfence();
    }
    __syncthreads();
}

// smem tile: 128 rows x 32 fp16, padded to 40/row
#define TROW   40
#define TILE_B (128 * TROW * 2)    // 10240 bytes
#define STAGE1_B (2 * TILE_B)      // Ah, Bh          (1-term)
#define STAGE2_B (3 * TILE_B)      // Ah, Bh, Bl      (2-term, powers only)
#define GEMM_SMEM (2 * STAGE1_B)   // 40960
#define MEGA_SMEM 70656            // boundary chain: 2*128*69*4; >= 2*STAGE2_B

// ================= 1-term pipeline =================
__device__ __forceinline__ void stage_load1(
    uint32_t sbase, int buf,
    const __half* __restrict__ Ah, const __half* __restrict__ Bh,
    int row0, int col0, int k0, int tid)
{
    const __half* gp0 = Ah + (size_t)row0 * CN + k0;
    const __half* gp1 = Bh + (size_t)col0 * CN + k0;
    uint32_t base = sbase + buf * STAGE1_B;
#pragma unroll
    for (int u = 0; u < 2; u++) {
        int e = tid + u * 256;
        int r = e >> 2, cu = e & 3;
        uint32_t off = (uint32_t)(r * (TROW * 2) + cu * 16);
        size_t gs = (size_t)r * CN + cu * 8;
        cp16(base + off, gp0 + gs);
        cp16(base + TILE_B + off, gp1 + gs);
    }
}

__device__ __forceinline__ void stage_compute1(
    uint32_t sbase, int buf, int wm, int wn, int lane, float acc[4][4][4])
{
    const uint32_t b0 = sbase + buf * STAGE1_B;
    const uint32_t aH = b0, bH = b0 + TILE_B;
    const int arow = wm * 64 + (lane & 15);
    const int brow = wn * 32 + (lane & 7) + ((lane >> 4) & 1) * 8;
#pragma unroll
    for (int k16 = 0; k16 < 2; k16++) {
        const int akc = k16 * 16 + (lane >> 4) * 8;
        const int bkc = k16 * 16 + ((lane >> 3) & 1) * 8;
        uint32_t af[4][4], bh[2][4];
#pragma unroll
        for (int mi = 0; mi < 4; mi++)
            ldsm4(af[mi][0], af[mi][1], af[mi][2], af[mi][3],
                  aH + (uint32_t)((arow + mi * 16) * (TROW * 2) + akc * 2));
#pragma unroll
        for (int nf = 0; nf < 2; nf++)
            ldsm4(bh[nf][0], bh[nf][1], bh[nf][2], bh[nf][3],
                  bH + (uint32_t)((brow + nf * 16) * (TROW * 2) + bkc * 2));
#pragma unroll
        for (int mi = 0; mi < 4; mi++)
#pragma unroll
            for (int nf = 0; nf < 2; nf++)
#pragma unroll
                for (int sub = 0; sub < 2; sub++)
                    mma16816(acc[mi][nf * 2 + sub], af[mi], bh[nf][sub * 2], bh[nf][sub * 2 + 1]);
    }
}

__device__ __forceinline__ void gemm_core1(
    uint32_t sbase, int tid, int wm, int wn, int lane,
    const __half* Ah, const __half* Bh,
    int row0, int col0, float acc[4][4][4])
{
#pragma unroll
    for (int i = 0; i < 4; i++)
#pragma unroll
        for (int j = 0; j < 4; j++)
#pragma unroll
            for (int r = 0; r < 4; r++) acc[i][j][r] = 0.f;
    stage_load1(sbase, 0, Ah, Bh, row0, col0, 0, tid);
    cp_commit();
    const int NS = CN / 32;
    for (int s = 0; s < NS; s++) {
        cp_wait0();
        __syncthreads();
        if (s + 1 < NS) {
            stage_load1(sbase, (s + 1) & 1, Ah, Bh, row0, col0, (s + 1) * 32, tid);
            cp_commit();
        }
        stage_compute1(sbase, s & 1, wm, wn, lane, acc);
        __syncthreads();
    }
}

// ================= 2-term pipeline (powers only) =================
__device__ __forceinline__ void stage_load2(
    uint32_t sbase, int buf,
    const __half* __restrict__ Ah,
    const __half* __restrict__ Bh, const __half* __restrict__ Bl,
    int row0, int col0, int k0, int tid)
{
    const __half* gp0 = Ah + (size_t)row0 * CN + k0;
    const __half* gp1 = Bh + (size_t)col0 * CN + k0;
    const __half* gp2 = Bl + (size_t)col0 * CN + k0;
    uint32_t base = sbase + buf * STAGE2_B;
#pragma unroll
    for (int u = 0; u < 2; u++) {
        int e = tid + u * 256;
        int r = e >> 2, cu = e & 3;
        uint32_t off = (uint32_t)(r * (TROW * 2) + cu * 16);
        size_t gs = (size_t)r * CN + cu * 8;
        cp16(base + off, gp0 + gs);
        cp16(base + TILE_B + off, gp1 + gs);
        cp16(base + 2 * TILE_B + off, gp2 + gs);
    }
}

__device__ __forceinline__ void stage_compute2(
    uint32_t sbase, int buf, int wm, int wn, int lane, float acc[4][4][4])
{
    const uint32_t b0 = sbase + buf * STAGE2_B;
    const uint32_t aH = b0, bH = b0 + TILE_B, bL = b0 + 2 * TILE_B;
    const int arow = wm * 64 + (lane & 15);
    const int brow = wn * 32 + (lane & 7) + ((lane >> 4) & 1) * 8;
#pragma unroll
    for (int k16 = 0; k16 < 2; k16++) {
        const int akc = k16 * 16 + (lane >> 4) * 8;
        const int bkc = k16 * 16 + ((lane >> 3) & 1) * 8;
        uint32_t af[4][4], bh[2][4], bl[2][4];
#pragma unroll
        for (int mi = 0; mi < 4; mi++)
            ldsm4(af[mi][0], af[mi][1], af[mi][2], af[mi][3],
                  aH + (uint32_t)((arow + mi * 16) * (TROW * 2) + akc * 2));
#pragma unroll
        for (int nf = 0; nf < 2; nf++)
            ldsm4(bh[nf][0], bh[nf][1], bh[nf][2], bh[nf][3],
                  bH + (uint32_t)((brow + nf * 16) * (TROW * 2) + bkc * 2));
#pragma unroll
        for (int nf = 0; nf < 2; nf++)
            ldsm4(bl[nf][0], bl[nf][1], bl[nf][2], bl[nf][3],
                  bL + (uint32_t)((brow + nf * 16) * (TROW * 2) + bkc * 2));
#pragma unroll
        for (int mi = 0; mi < 4; mi++)
#pragma unroll
            for (int nf = 0; nf < 2; nf++)
#pragma unroll
                for (int sub = 0; sub < 2; sub++) {
                    mma16816(acc[mi][nf * 2 + sub], af[mi], bh[nf][sub * 2], bh[nf][sub * 2 + 1]);
                    mma16816(acc[mi][nf * 2 + sub], af[mi], bl[nf][sub * 2], bl[nf][sub * 2 + 1]);
                }
    }
}

__device__ __forceinline__ void gemm_core2(
    uint32_t sbase, int tid, int wm, int wn, int lane,
    const __half* Ah, const __half* Bh, const __half* Bl,
    int row0, int col0, float acc[4][4][4])
{
#pragma unroll
    for (int i = 0; i < 4; i++)
#pragma unroll
        for (int j = 0; j < 4; j++)
#pragma unroll
            for (int r = 0; r < 4; r++) acc[i][j][r] = 0.f;
    stage_load2(sbase, 0, Ah, Bh, Bl, row0, col0, 0, tid);
    cp_commit();
    const int NS = CN / 32;
    for (int s = 0; s < NS; s++) {
        cp_wait0();
        __syncthreads();
        if (s + 1 < NS) {
            stage_load2(sbase, (s + 1) & 1, Ah, Bh, Bl, row0, col0, (s + 1) * 32, tid);
            cp_commit();
        }
        stage_compute2(sbase, s & 1, wm, wn, lane, acc);
        __syncthreads();
    }
}

// ---------------- step epilogue ----------------
__device__ __forceinline__ void step_epi(
    float acc[4][4][4], int row0, int col0, int wm, int wn, int lane,
    const float* __restrict__ xp, int jstep,
    float* __restrict__ f32out,
    __half* __restrict__ sh, __half* __restrict__ oah)
{
#pragma unroll
    for (int mi = 0; mi < 4; mi++) {
        const int rbase = row0 + wm * 64 + mi * 16 + (lane >> 2);
#pragma unroll
        for (int half = 0; half < 2; half++) {
            const int m = rbase + half * 8;
            const int bb = m >> 5, blk = m & 31;
            const size_t xoff = ((size_t)bb * CT + blk * S_ + jstep) * CN;
#pragma unroll
            for (int ni = 0; ni < 4; ni++) {
                const int c = col0 + wn * 32 + ni * 8 + (lane & 3) * 2;
                float2 x = *(const float2*)&xp[xoff + c];
                float v0 = acc[mi][ni][half * 2 + 0] + x.x;
                float v1 = acc[mi][ni][half * 2 + 1] + x.y;
                if (f32out)
                    *(float2*)&f32out[(size_t)m * CN + c] = make_float2(v0, v1);
                __half2 h = __floats2half2_rn(v0, v1);
                *(__half2*)&sh[(size_t)m * CN + c] = h;
                if (oah)
                    *(__half2*)&oah[xoff + c] = h;
            }
        }
    }
}

// =====================================================================
// PERSISTENT MEGA KERNEL
// =====================================================================
__global__ __launch_bounds__(256, 1) void mega_k(
    const float* __restrict__ xp,
    __half* p1h, __half* p2h, __half* q2h, __half* q2l,
    const __half* wah, const __half* wal, const __half* wth,
    float* s1, float* bd, float* pA, float* pB, float* part,
    __half* ah)
{
    extern __shared__ char smem[];
    const uint32_t sbase = smem_u32(smem);
    const int tid = threadIdx.x, lane = tid & 31, w = tid >> 5;
    const int wm = w & 1, wn = w >> 1;
    const int bid = blockIdx.x;
    const int row0 = (bid >> 3) * 128;
    const int col0 = (bid & 7) * 128;

    // ===== init1: p1h <- fp16(Xp[t=blk*16]) =====
    {
        const size_t base = (size_t)bid * 16384;
#pragma unroll
        for (int i = 0; i < 16; i++) {
            const size_t e = base + (size_t)(tid + i * 256) * 4;
            const int r = (int)(e >> 10), n = (int)(e & 1023);
            const int bb = r >> 5, blk = r & 31;
            float4 v = *(const float4*)&xp[((size_t)bb * CT + blk * S_) * CN + n];
            *(__half2*)&p1h[e]     = __floats2half2_rn(v.x, v.y);
            *(__half2*)&p1h[e + 2] = __floats2half2_rn(v.z, v.w);
        }
    }
    grid_sync();

    // ===== pass1: j = 1..15 (1-term) =====
    for (int j = 1; j < S_; j++) {
        const bool in1 = (j & 1);
        const __half* ih = in1 ? p1h : p2h;
        __half* oh = in1 ? p2h : p1h;
        float acc[4][4][4];
        gemm_core1(sbase, tid, wm, wn, lane, ih, wah, row0, col0, acc);
        step_epi(acc, row0, col0, wm, wn, lane, xp, j,
                 (j == S_ - 1) ? s1 : nullptr, oh, nullptr);
        grid_sync();
    }

    // ===== powers: R16T = (Waa^16)^T via 4 levels (2-term B-side) =====
    {
        for (int lvl = 0; lvl < 4; lvl++) {
            const __half *iah, *ibh, *ibl;
            float* G = (lvl & 1) ? pB : pA;
            if (lvl == 0) { iah = wth; ibh = wah; ibl = wal; }
            else          { iah = p1h; ibh = q2h; ibl = q2l; }
            if (bid < 64) {
                float acc[4][4][4];
                gemm_core2(sbase, tid, wm, wn, lane, iah, ibh, ibl,
                           (bid >> 3) * 128, (bid & 7) * 128, acc);
#pragma unroll
                for (int mi = 0; mi < 4; mi++) {
                    const int rb = (bid >> 3) * 128 + wm * 64 + mi * 16 + (lane >> 2);
#pragma unroll
                    for (int half = 0; half < 2; half++) {
                        const int m = rb + half * 8;
#pragma unroll
                        for (int ni = 0; ni < 4; ni++) {
                            const int c = (bid & 7) * 128 + wn * 32 + ni * 8 + (lane & 3) * 2;
                            *(float2*)&G[(size_t)m * CN + c] =
                                make_float2(acc[mi][ni][half * 2 + 0], acc[mi][ni][half * 2 + 1]);
                        }
                    }
                }
            }
            grid_sync();
            if (lvl < 3) {
                float (*ts)[33] = (float(*)[33])smem;
                for (int t8 = 0; t8 < 8; t8++) {
                    const int tile = bid * 8 + t8;
                    const int tr = tile >> 5, tc = tile & 31;
                    const int x = tid & 31, y8 = tid >> 5;
                    __syncthreads();
#pragma unroll
                    for (int p = 0; p < 4; p++) {
                        const int y = y8 + p * 8;
                        float v = G[(size_t)(tr * 32 + y) * CN + tc * 32 + x];
                        ts[y][x] = v;
                        p1h[(size_t)(tr * 32 + y) * CN + tc * 32 + x] = __float2half_rn(v);
                    }
                    __syncthreads();
#pragma unroll
                    for (int p = 0; p < 4; p++) {
                        const int y = y8 + p * 8;
                        float v = ts[x][y];
                        __half h = __float2half_rn(v);
                        const size_t di = (size_t)(tc * 32 + y) * CN + tr * 32 + x;
                        q2h[di] = h;
                        q2l[di] = __float2half_rn(v - __half2float(h));
                    }
                }
                grid_sync();
            }
        }
    }
    // pB holds R16T = (Waa^16)^T fp32

    // ===== boundary chain (fp32) =====
    {
        {
            const size_t e = (size_t)bid * 512 + tid * 2;
            const int m = (int)(e >> 10), n = (int)(e & 1023);
            *(float2*)&bd[e] = *(const float2*)&s1[((size_t)(m * NBLK + 0)) * CN + n];
        }
        grid_sync();

        const int nb = bid & 15, kb = bid >> 4;
        float (*Ps)[69] = (float(*)[69])smem;
        float (*Bs)[69] = (float(*)[69])(smem + 128 * 69 * 4);
        for (int i = 0; i < 32; i++) {
            const int e = tid + i * 256;
            const int kk = e >> 6, n = e & 63;
            Ps[kk][n] = pB[(size_t)(kb * 128 + kk) * CN + nb * 64 + n];
        }
        const int tm = tid & 15, tn = tid >> 4;
        for (int k = 1; k < NBLK; k++) {
            const float* bsrc = bd + (size_t)(k - 1) * CB * CN;
            for (int i = 0; i < 32; i++) {
                const int e = tid + i * 256;
                const int m = e >> 7, kk = e & 127;
                Bs[kk][m] = bsrc[(size_t)m * CN + kb * 128 + kk];
            }
            __syncthreads();
            float acc[4][4];
#pragma unroll
            for (int i = 0; i < 4; i++)
#pragma unroll
                for (int j = 0; j < 4; j++) acc[i][j] = 0.f;
            for (int kk = 0; kk < 128; kk++) {
                float a0 = Bs[kk][tm * 4 + 0], a1 = Bs[kk][tm * 4 + 1];
                float a2 = Bs[kk][tm * 4 + 2], a3 = Bs[kk][tm * 4 + 3];
                float w0 = Ps[kk][tn * 4 + 0], w1 = Ps[kk][tn * 4 + 1];
                float w2 = Ps[kk][tn * 4 + 2], w3 = Ps[kk][tn * 4 + 3];
                acc[0][0] += a0 * w0; acc[0][1] += a0 * w1; acc[0][2] += a0 * w2; acc[0][3] += a0 * w3;
                acc[1][0] += a1 * w0; acc[1][1] += a1 * w1; acc[1][2] += a1 * w2; acc[1][3] += a1 * w3;
                acc[2][0] += a2 * w0; acc[2][1] += a2 * w1; acc[2][2] += a2 * w2; acc[2][3] += a2 * w3;
                acc[3][0] += a3 * w0; acc[3][1] += a3 * w1; acc[3][2] += a3 * w2; acc[3][3] += a3 * w3;
            }
            float* dst = part + (size_t)kb * CB * CN;
#pragma unroll
            for (int i = 0; i < 4; i++) {
                const int m = tm * 4 + i;
                *(float4*)&dst[(size_t)m * CN + nb * 64 + tn * 4] =
                    make_float4(acc[i][0], acc[i][1], acc[i][2], acc[i][3]);
            }
            grid_sync();
            {
                const size_t e = (size_t)bid * 512 + tid * 2;
                const int m = (int)(e >> 10), n = (int)(e & 1023);
                float2 v = *(const float2*)&s1[((size_t)(m * NBLK + k)) * CN + n];
#pragma unroll
                for (int s = 0; s < 8; s++) {
                    float2 p = *(const float2*)&part[(size_t)s * CB * CN + e];
                    v.x += p.x; v.y += p.y;
                }
                *(float2*)&bd[(size_t)k * CB * CN + e] = v;
            }
            grid_sync();
        }
    }

    // ===== init3: p1h <- fp16(seed) =====
    {
        const size_t base = (size_t)bid * 16384;
#pragma unroll
        for (int i = 0; i < 16; i++) {
            const size_t e = base + (size_t)(tid + i * 256) * 4;
            const int r = (int)(e >> 10), n = (int)(e & 1023);
            const int bb = r >> 5, blk = r & 31;
            float4 v = make_float4(0.f, 0.f, 0.f, 0.f);
            if (blk) v = *(const float4*)&bd[((size_t)(blk - 1) * CB + bb) * CN + n];
            *(__half2*)&p1h[e]     = __floats2half2_rn(v.x, v.y);
            *(__half2*)&p1h[e + 2] = __floats2half2_rn(v.z, v.w);
        }
    }
    grid_sync();

    // ===== pass3: j = 0..15 (1-term) =====
    for (int j = 0; j < S_; j++) {
        const bool in1 = ((j & 1) == 0);
        const __half* ih = in1 ? p1h : p2h;
        __half* oh = in1 ? p2h : p1h;
        float acc[4][4][4];
        gemm_core1(sbase, tid, wm, wn, lane, ih, wah, row0, col0, acc);
        step_epi(acc, row0, col0, wm, wn, lane, xp, j, nullptr, oh, ah);
        if (j < S_ - 1) grid_sync();
    }
}

// =====================================================================
// Standalone big GEMM (phase A / Y): C = A@W^T + bias, 1-term
// =====================================================================
__global__ __launch_bounds__(256, 2) void mma_gemm_bias(
    const __half* __restrict__ Ah, const __half* __restrict__ Bh,
    const float* __restrict__ bias, float* __restrict__ out)
{
    extern __shared__ char smem[];
    const uint32_t sbase = smem_u32(smem);
    const int tid = threadIdx.x, lane = tid & 31, w = tid >> 5;
    const int wm = w & 1, wn = w >> 1;
    const int row0 = blockIdx.y * 128, col0 = blockIdx.x * 128;
    float acc[4][4][4];
    gemm_core1(sbase, tid, wm, wn, lane, Ah, Bh, row0, col0, acc);
#pragma unroll
    for (int mi = 0; mi < 4; mi++) {
        const int rbase = row0 + wm * 64 + mi * 16 + (lane >> 2);
#pragma unroll
        for (int half = 0; half < 2; half++) {
            const int m = rbase + half * 8;
#pragma unroll
            for (int ni = 0; ni < 4; ni++) {
                const int c = col0 + wn * 32 + ni * 8 + (lane & 3) * 2;
                float v0 = acc[mi][ni][half * 2 + 0] + bias[c];
                float v1 = acc[mi][ni][half * 2 + 1] + bias[c + 1];
                *(float2*)&out[(size_t)m * CN + c] = make_float2(v0, v1);
            }
        }
    }
}

// ---------------- prep kernels ----------------
__global__ __launch_bounds__(256) void hsplit_k(
    const float* __restrict__ src, __half* __restrict__ hi)
{
    const size_t e = ((size_t)blockIdx.x * 256 + threadIdx.x) * 4;
    float4 v = *(const float4*)&src[e];
    *(__half2*)&hi[e]     = __floats2half2_rn(v.x, v.y);
    *(__half2*)&hi[e + 2] = __floats2half2_rn(v.z, v.w);
}

__global__ __launch_bounds__(256) void wsplit_k(
    const float* __restrict__ src, __half* __restrict__ hi, __half* __restrict__ lo)
{
    const size_t e = ((size_t)blockIdx.x * 256 + threadIdx.x) * 4;
    float4 v = *(const float4*)&src[e];
    __half h0 = __float2half_rn(v.x), h1 = __float2half_rn(v.y);
    __half h2 = __float2half_rn(v.z), h3 = __float2half_rn(v.w);
    hi[e] = h0; hi[e + 1] = h1; hi[e + 2] = h2; hi[e + 3] = h3;
    lo[e]     = __float2half_rn(v.x - __half2float(h0));
    lo[e + 1] = __float2half_rn(v.y - __half2float(h1));
    lo[e + 2] = __float2half_rn(v.z - __half2float(h2));
    lo[e + 3] = __float2half_rn(v.w - __half2float(h3));
}

__global__ __launch_bounds__(256) void tsplit_k(
    const float* __restrict__ src, __half* __restrict__ hi)
{
    __shared__ float ts[32][33];
    const int x = threadIdx.x & 31, y8 = threadIdx.x >> 5;
    const int tr = blockIdx.y, tc = blockIdx.x;
#pragma unroll
    for (int p = 0; p < 4; p++) {
        const int y = y8 + p * 8;
        ts[y][x] = src[(size_t)(tr * 32 + y) * CN + tc * 32 + x];
    }
    __syncthreads();
#pragma unroll
    for (int p = 0; p < 4; p++) {
        const int y = y8 + p * 8;
        hi[(size_t)(tc * 32 + y) * CN + tr * 32 + x] = __float2half_rn(ts[x][y]);
    }
}

// =====================================================================
// host
// =====================================================================
extern "C" void kernel_launch(void* const* d_in, const int* in_sizes, int n_in,
                              void* d_out, int out_size)
{
    const float* X   = (const float*)d_in[0];
    const float* Wax = (const float*)d_in[1];
    const float* Waa = (const float*)d_in[2];
    const float* ba  = (const float*)d_in[3];
    const float* Wy  = (const float*)d_in[4];
    const float* by  = (const float*)d_in[5];
    float* Y = (float*)d_out;

    void *xpv, *xhv, *ahv, *s1v, *p1hv, *p2hv, *q2hv, *q2lv;
    void *wxhv, *wahv, *walv, *wyhv, *wthv;
    void *bdv, *pAv, *pBv, *partv;
    cudaGetSymbolAddress(&xpv, g_xp);   cudaGetSymbolAddress(&xhv, g_xh);
    cudaGetSymbolAddress(&ahv, g_ah);   cudaGetSymbolAddress(&s1v, g_s1);
    cudaGetSymbolAddress(&p1hv, g_p1h); cudaGetSymbolAddress(&p2hv, g_p2h);
    cudaGetSymbolAddress(&q2hv, g_q2h); cudaGetSymbolAddress(&q2lv, g_q2l);
    cudaGetSymbolAddress(&wxhv, g_wxh);
    cudaGetSymbolAddress(&wahv, g_wah); cudaGetSymbolAddress(&walv, g_wal);
    cudaGetSymbolAddress(&wyhv, g_wyh); cudaGetSymbolAddress(&wthv, g_wth);
    cudaGetSymbolAddress(&bdv, g_bd);   cudaGetSymbolAddress(&pAv, g_pA);
    cudaGetSymbolAddress(&pBv, g_pB);   cudaGetSymbolAddress(&partv, g_part);

    float* xp = (float*)xpv; float* s1 = (float*)s1v;
    float* bd = (float*)bdv; float* pA = (float*)pAv; float* pB = (float*)pBv;
    float* part = (float*)partv;
    __half* xh  = (__half*)xhv;  __half* ah  = (__half*)ahv;
    __half* p1h = (__half*)p1hv; __half* p2h = (__half*)p2hv;
    __half* q2h = (__half*)q2hv; __half* q2l = (__half*)q2lv;
    __half* wxh = (__half*)wxhv;
    __half* wah = (__half*)wahv; __half* wal = (__half*)walv;
    __half* wyh = (__half*)wyhv; __half* wth = (__half*)wthv;

    cudaFuncSetAttribute(mma_gemm_bias, cudaFuncAttributeMaxDynamicSharedMemorySize, GEMM_SMEM);
    cudaFuncSetAttribute(mega_k,        cudaFuncAttributeMaxDynamicSharedMemorySize, MEGA_SMEM);

    // ---- prep ----
    hsplit_k<<<(MROWS * CN) / 1024, 256>>>(X, xh);
    hsplit_k<<<(CN * CN) / 1024, 256>>>(Wax, wxh);
    hsplit_k<<<(CN * CN) / 1024, 256>>>(Wy, wyh);
    wsplit_k<<<(CN * CN) / 1024, 256>>>(Waa, wah, wal);
    tsplit_k<<<dim3(32, 32), 256>>>(Waa, wth);

    // ---- Phase A: Xp = X @ Wax^T + ba ----
    mma_gemm_bias<<<dim3(CN / 128, MROWS / 128), 256, GEMM_SMEM>>>(
        xh, wxh, ba, xp);

    // ---- persistent middle ----
    mega_k<<<NCTA, 256, MEGA_SMEM>>>(
        xp, p1h, p2h, q2h, q2l, wah, wal, wth,
        s1, bd, pA, pB, part, ah);

    // ---- Phase Y: Y = A @ Wy^T + by ----
    mma_gemm_bias<<<dim3(CN / 128, MROWS / 128), 256, GEMM_SMEM>>>(
        ah, wyh, by, Y);
}

// round 8
// speedup vs baseline: 4.6028x; 1.1041x over previous
#include <cuda_runtime.h>
#include <cuda_fp16.h>
#include <cstdint>

// ---------------- problem constants ----------------
#define CB   64
#define CT   512
#define CD   1024
#define CN   1024
#define S_   16
#define NBLK 32
#define MROWS (CB * CT)    // 32768
#define MST   (CB * NBLK)  // 2048
#define NCTA  128          // persistent grid (one wave)

// ---------------- scratch ----------------
__device__ float   g_xp [(size_t)MROWS * CN];   // Xp fp32 (step addend)
__device__ __half  g_xh [(size_t)MROWS * CN];   // X hi plane
__device__ __half  g_ah [(size_t)MROWS * CN];   // a_t hi plane (phase-Y A-side)
__device__ float   g_s1 [(size_t)MST * CN];     // E states fp32
__device__ __half  g_p1h[(size_t)MST * CN];     // state ping
__device__ __half  g_p2h[(size_t)MST * CN];     // state pong
__device__ __half  g_q2h[(size_t)CN * CN];      // powers B-side hi
__device__ __half  g_q2l[(size_t)CN * CN];      // powers B-side lo
__device__ __half  g_wxh[(size_t)CN * CN];
__device__ __half  g_wah[(size_t)CN * CN], g_wal[(size_t)CN * CN];
__device__ __half  g_wyh[(size_t)CN * CN];
__device__ __half  g_wth[(size_t)CN * CN];      // Waa^T hi
__device__ float g_bd[(size_t)NBLK * CB * CN];
__device__ float g_pA[(size_t)CN * CN];
__device__ float g_pB[(size_t)CN * CN];
__device__ float g_part[(size_t)8 * CB * CN];
__device__ unsigned g_cnt;
__device__ unsigned g_gen;

// =====================================================================
// Portable PTX helpers (sm_80-class only)
// =====================================================================
__device__ __forceinline__ uint32_t smem_u32(const void* p) {
    return (uint32_t)__cvta_generic_to_shared(p);
}
__device__ __forceinline__ void cp16(uint32_t dst, const void* src) {
    asm volatile("cp.async.cg.shared.global [%0], [%1], 16;\n" :: "r"(dst), "l"(src));
}
__device__ __forceinline__ void cp_commit() {
    asm volatile("cp.async.commit_group;\n" ::: "memory");
}
__device__ __forceinline__ void cp_wait0() {
    asm volatile("cp.async.wait_group 0;\n" ::: "memory");
}
__device__ __forceinline__ void cp_wait1() {
    asm volatile("cp.async.wait_group 1;\n" ::: "memory");
}
__device__ __forceinline__ void ldsm4(uint32_t& r0, uint32_t& r1, uint32_t& r2, uint32_t& r3, uint32_t a) {
    asm volatile("ldmatrix.sync.aligned.m8n8.x4.shared.b16 {%0,%1,%2,%3}, [%4];\n"
                 : "=r"(r0), "=r"(r1), "=r"(r2), "=r"(r3) : "r"(a));
}
__device__ __forceinline__ void mma16816(float* d, const uint32_t* a, uint32_t b0, uint32_t b1) {
    asm volatile(
        "mma.sync.aligned.m16n8k16.row.col.f32.f16.f16.f32 "
        "{%0,%1,%2,%3}, {%4,%5,%6,%7}, {%8,%9}, {%0,%1,%2,%3};\n"
        : "+f"(d[0]), "+f"(d[1]), "+f"(d[2]), "+f"(d[3])
        : "r"(a[0]), "r"(a[1]), "r"(a[2]), "r"(a[3]), "r"(b0), "r"(b1));
}

// grid-wide barrier: sense-reversing, deterministic, replay-safe
__device__ __forceinline__ void grid_sync() {
    __syncthreads();
    if (threadIdx.x == 0) {
        __threadfence();
        volatile unsigned* gen = &g_gen;
        unsigned my = *gen;
        unsigned old = atomicAdd(&g_cnt, 1u);
        if (old == (unsigned)(NCTA - 1)) {
            g_cnt = 0u;
            __threadfence();
            *gen = my + 1u;
        } else {
            while (*gen == my) { }
        }
        __threadfence();
    }
    __syncthreads();
}

// smem tile: 128 rows x 32 fp16, padded to 40/row
#define TROW   40
#define TILE_B (128 * TROW * 2)    // 10240 bytes
#define STAGE1_B (2 * TILE_B)      // Ah, Bh          (1-term)
#define STAGE2_B (3 * TILE_B)      // Ah, Bh, Bl      (2-term, powers only)
#define GEMM_SMEM (3 * STAGE1_B)   // 61440, 3-stage
#define MEGA_SMEM (3 * STAGE2_B)   // 92160, 3-stage (boundary/transpose fit inside)

// ================= 1-term 3-stage pipeline =================
__device__ __forceinline__ void stage_load1(
    uint32_t sbase, int buf,
    const __half* __restrict__ Ah, const __half* __restrict__ Bh,
    int row0, int col0, int k0, int tid)
{
    const __half* gp0 = Ah + (size_t)row0 * CN + k0;
    const __half* gp1 = Bh + (size_t)col0 * CN + k0;
    uint32_t base = sbase + buf * STAGE1_B;
#pragma unroll
    for (int u = 0; u < 2; u++) {
        int e = tid + u * 256;
        int r = e >> 2, cu = e & 3;
        uint32_t off = (uint32_t)(r * (TROW * 2) + cu * 16);
        size_t gs = (size_t)r * CN + cu * 8;
        cp16(base + off, gp0 + gs);
        cp16(base + TILE_B + off, gp1 + gs);
    }
}

__device__ __forceinline__ void stage_compute1(
    uint32_t sbase, int buf, int wm, int wn, int lane, float acc[4][4][4])
{
    const uint32_t b0 = sbase + buf * STAGE1_B;
    const uint32_t aH = b0, bH = b0 + TILE_B;
    const int arow = wm * 64 + (lane & 15);
    const int brow = wn * 32 + (lane & 7) + ((lane >> 4) & 1) * 8;
#pragma unroll
    for (int k16 = 0; k16 < 2; k16++) {
        const int akc = k16 * 16 + (lane >> 4) * 8;
        const int bkc = k16 * 16 + ((lane >> 3) & 1) * 8;
        uint32_t af[4][4], bh[2][4];
#pragma unroll
        for (int mi = 0; mi < 4; mi++)
            ldsm4(af[mi][0], af[mi][1], af[mi][2], af[mi][3],
                  aH + (uint32_t)((arow + mi * 16) * (TROW * 2) + akc * 2));
#pragma unroll
        for (int nf = 0; nf < 2; nf++)
            ldsm4(bh[nf][0], bh[nf][1], bh[nf][2], bh[nf][3],
                  bH + (uint32_t)((brow + nf * 16) * (TROW * 2) + bkc * 2));
#pragma unroll
        for (int mi = 0; mi < 4; mi++)
#pragma unroll
            for (int nf = 0; nf < 2; nf++)
#pragma unroll
                for (int sub = 0; sub < 2; sub++)
                    mma16816(acc[mi][nf * 2 + sub], af[mi], bh[nf][sub * 2], bh[nf][sub * 2 + 1]);
    }
}

__device__ __forceinline__ void gemm_core1(
    uint32_t sbase, int tid, int wm, int wn, int lane,
    const __half* Ah, const __half* Bh,
    int row0, int col0, float acc[4][4][4])
{
#pragma unroll
    for (int i = 0; i < 4; i++)
#pragma unroll
        for (int j = 0; j < 4; j++)
#pragma unroll
            for (int r = 0; r < 4; r++) acc[i][j][r] = 0.f;
    stage_load1(sbase, 0, Ah, Bh, row0, col0, 0, tid);
    cp_commit();
    stage_load1(sbase, 1, Ah, Bh, row0, col0, 32, tid);
    cp_commit();
    const int NS = CN / 32;
    for (int s = 0; s < NS; s++) {
        if (s + 1 < NS) cp_wait1(); else cp_wait0();
        __syncthreads();
        if (s + 2 < NS) {
            stage_load1(sbase, (s + 2) % 3, Ah, Bh, row0, col0, (s + 2) * 32, tid);
            cp_commit();
        }
        stage_compute1(sbase, s % 3, wm, wn, lane, acc);
    }
}

// ================= 2-term 3-stage pipeline (powers only) =================
__device__ __forceinline__ void stage_load2(
    uint32_t sbase, int buf,
    const __half* __restrict__ Ah,
    const __half* __restrict__ Bh, const __half* __restrict__ Bl,
    int row0, int col0, int k0, int tid)
{
    const __half* gp0 = Ah + (size_t)row0 * CN + k0;
    const __half* gp1 = Bh + (size_t)col0 * CN + k0;
    const __half* gp2 = Bl + (size_t)col0 * CN + k0;
    uint32_t base = sbase + buf * STAGE2_B;
#pragma unroll
    for (int u = 0; u < 2; u++) {
        int e = tid + u * 256;
        int r = e >> 2, cu = e & 3;
        uint32_t off = (uint32_t)(r * (TROW * 2) + cu * 16);
        size_t gs = (size_t)r * CN + cu * 8;
        cp16(base + off, gp0 + gs);
        cp16(base + TILE_B + off, gp1 + gs);
        cp16(base + 2 * TILE_B + off, gp2 + gs);
    }
}

__device__ __forceinline__ void stage_compute2(
    uint32_t sbase, int buf, int wm, int wn, int lane, float acc[4][4][4])
{
    const uint32_t b0 = sbase + buf * STAGE2_B;
    const uint32_t aH = b0, bH = b0 + TILE_B, bL = b0 + 2 * TILE_B;
    const int arow = wm * 64 + (lane & 15);
    const int brow = wn * 32 + (lane & 7) + ((lane >> 4) & 1) * 8;
#pragma unroll
    for (int k16 = 0; k16 < 2; k16++) {
        const int akc = k16 * 16 + (lane >> 4) * 8;
        const int bkc = k16 * 16 + ((lane >> 3) & 1) * 8;
        uint32_t af[4][4], bh[2][4], bl[2][4];
#pragma unroll
        for (int mi = 0; mi < 4; mi++)
            ldsm4(af[mi][0], af[mi][1], af[mi][2], af[mi][3],
                  aH + (uint32_t)((arow + mi * 16) * (TROW * 2) + akc * 2));
#pragma unroll
        for (int nf = 0; nf < 2; nf++)
            ldsm4(bh[nf][0], bh[nf][1], bh[nf][2], bh[nf][3],
                  bH + (uint32_t)((brow + nf * 16) * (TROW * 2) + bkc * 2));
#pragma unroll
        for (int nf = 0; nf < 2; nf++)
            ldsm4(bl[nf][0], bl[nf][1], bl[nf][2], bl[nf][3],
                  bL + (uint32_t)((brow + nf * 16) * (TROW * 2) + bkc * 2));
#pragma unroll
        for (int mi = 0; mi < 4; mi++)
#pragma unroll
            for (int nf = 0; nf < 2; nf++)
#pragma unroll
                for (int sub = 0; sub < 2; sub++) {
                    mma16816(acc[mi][nf * 2 + sub], af[mi], bh[nf][sub * 2], bh[nf][sub * 2 + 1]);
                    mma16816(acc[mi][nf * 2 + sub], af[mi], bl[nf][sub * 2], bl[nf][sub * 2 + 1]);
                }
    }
}

__device__ __forceinline__ void gemm_core2(
    uint32_t sbase, int tid, int wm, int wn, int lane,
    const __half* Ah, const __half* Bh, const __half* Bl,
    int row0, int col0, float acc[4][4][4])
{
#pragma unroll
    for (int i = 0; i < 4; i++)
#pragma unroll
        for (int j = 0; j < 4; j++)
#pragma unroll
            for (int r = 0; r < 4; r++) acc[i][j][r] = 0.f;
    stage_load2(sbase, 0, Ah, Bh, Bl, row0, col0, 0, tid);
    cp_commit();
    stage_load2(sbase, 1, Ah, Bh, Bl, row0, col0, 32, tid);
    cp_commit();
    const int NS = CN / 32;
    for (int s = 0; s < NS; s++) {
        if (s + 1 < NS) cp_wait1(); else cp_wait0();
        __syncthreads();
        if (s + 2 < NS) {
            stage_load2(sbase, (s + 2) % 3, Ah, Bh, Bl, row0, col0, (s + 2) * 32, tid);
            cp_commit();
        }
        stage_compute2(sbase, s % 3, wm, wn, lane, acc);
    }
}

// ---------------- step epilogue ----------------
__device__ __forceinline__ void step_epi(
    float acc[4][4][4], int row0, int col0, int wm, int wn, int lane,
    const float* __restrict__ xp, int jstep,
    float* __restrict__ f32out,
    __half* __restrict__ sh, __half* __restrict__ oah)
{
#pragma unroll
    for (int mi = 0; mi < 4; mi++) {
        const int rbase = row0 + wm * 64 + mi * 16 + (lane >> 2);
#pragma unroll
        for (int half = 0; half < 2; half++) {
            const int m = rbase + half * 8;
            const int bb = m >> 5, blk = m & 31;
            const size_t xoff = ((size_t)bb * CT + blk * S_ + jstep) * CN;
#pragma unroll
            for (int ni = 0; ni < 4; ni++) {
                const int c = col0 + wn * 32 + ni * 8 + (lane & 3) * 2;
                float2 x = *(const float2*)&xp[xoff + c];
                float v0 = acc[mi][ni][half * 2 + 0] + x.x;
                float v1 = acc[mi][ni][half * 2 + 1] + x.y;
                if (f32out)
                    *(float2*)&f32out[(size_t)m * CN + c] = make_float2(v0, v1);
                __half2 h = __floats2half2_rn(v0, v1);
                *(__half2*)&sh[(size_t)m * CN + c] = h;
                if (oah)
                    *(__half2*)&oah[xoff + c] = h;
            }
        }
    }
}

// =====================================================================
// PERSISTENT MEGA KERNEL
// =====================================================================
__global__ __launch_bounds__(256, 1) void mega_k(
    const float* __restrict__ xp,
    __half* p1h, __half* p2h, __half* q2h, __half* q2l,
    const __half* wah, const __half* wal, const __half* wth,
    float* s1, float* bd, float* pA, float* pB, float* part,
    __half* ah)
{
    extern __shared__ char smem[];
    const uint32_t sbase = smem_u32(smem);
    const int tid = threadIdx.x, lane = tid & 31, w = tid >> 5;
    const int wm = w & 1, wn = w >> 1;
    const int bid = blockIdx.x;
    const int row0 = (bid >> 3) * 128;
    const int col0 = (bid & 7) * 128;

    // ===== init1: p1h <- fp16(Xp[t=blk*16]) =====
    {
        const size_t base = (size_t)bid * 16384;
#pragma unroll
        for (int i = 0; i < 16; i++) {
            const size_t e = base + (size_t)(tid + i * 256) * 4;
            const int r = (int)(e >> 10), n = (int)(e & 1023);
            const int bb = r >> 5, blk = r & 31;
            float4 v = *(const float4*)&xp[((size_t)bb * CT + blk * S_) * CN + n];
            *(__half2*)&p1h[e]     = __floats2half2_rn(v.x, v.y);
            *(__half2*)&p1h[e + 2] = __floats2half2_rn(v.z, v.w);
        }
    }
    grid_sync();

    // ===== pass1: j = 1..15 (1-term) =====
    for (int j = 1; j < S_; j++) {
        const bool in1 = (j & 1);
        const __half* ih = in1 ? p1h : p2h;
        __half* oh = in1 ? p2h : p1h;
        float acc[4][4][4];
        gemm_core1(sbase, tid, wm, wn, lane, ih, wah, row0, col0, acc);
        step_epi(acc, row0, col0, wm, wn, lane, xp, j,
                 (j == S_ - 1) ? s1 : nullptr, oh, nullptr);
        grid_sync();
    }

    // ===== powers: 4 levels (2-term B-side) =====
    {
        for (int lvl = 0; lvl < 4; lvl++) {
            const __half *iah, *ibh, *ibl;
            float* G = (lvl & 1) ? pB : pA;
            if (lvl == 0) { iah = wth; ibh = wah; ibl = wal; }
            else          { iah = p1h; ibh = q2h; ibl = q2l; }
            if (bid < 64) {
                float acc[4][4][4];
                gemm_core2(sbase, tid, wm, wn, lane, iah, ibh, ibl,
                           (bid >> 3) * 128, (bid & 7) * 128, acc);
#pragma unroll
                for (int mi = 0; mi < 4; mi++) {
                    const int rb = (bid >> 3) * 128 + wm * 64 + mi * 16 + (lane >> 2);
#pragma unroll
                    for (int half = 0; half < 2; half++) {
                        const int m = rb + half * 8;
#pragma unroll
                        for (int ni = 0; ni < 4; ni++) {
                            const int c = (bid & 7) * 128 + wn * 32 + ni * 8 + (lane & 3) * 2;
                            *(float2*)&G[(size_t)m * CN + c] =
                                make_float2(acc[mi][ni][half * 2 + 0], acc[mi][ni][half * 2 + 1]);
                        }
                    }
                }
            }
            grid_sync();
            if (lvl < 3) {
                float (*ts)[33] = (float(*)[33])smem;
                for (int t8 = 0; t8 < 8; t8++) {
                    const int tile = bid * 8 + t8;
                    const int tr = tile >> 5, tc = tile & 31;
                    const int x = tid & 31, y8 = tid >> 5;
                    __syncthreads();
#pragma unroll
                    for (int p = 0; p < 4; p++) {
                        const int y = y8 + p * 8;
                        float v = G[(size_t)(tr * 32 + y) * CN + tc * 32 + x];
                        ts[y][x] = v;
                        p1h[(size_t)(tr * 32 + y) * CN + tc * 32 + x] = __float2half_rn(v);
                    }
                    __syncthreads();
#pragma unroll
                    for (int p = 0; p < 4; p++) {
                        const int y = y8 + p * 8;
                        float v = ts[x][y];
                        __half h = __float2half_rn(v);
                        const size_t di = (size_t)(tc * 32 + y) * CN + tr * 32 + x;
                        q2h[di] = h;
                        q2l[di] = __float2half_rn(v - __half2float(h));
                    }
                }
                grid_sync();
            }
        }
    }
    // pB holds the K-major boundary operator (validated: bd_next = bd @ pB)

    // ===== boundary chain (fp16 tensor-core) =====
    {
        // b_0 init
        {
            const size_t e = (size_t)bid * 512 + tid * 2;
            const int m = (int)(e >> 10), n = (int)(e & 1023);
            *(float2*)&bd[e] = *(const float2*)&s1[((size_t)(m * NBLK + 0)) * CN + n];
        }

        const int nb = bid & 15, kb = bid >> 4;
        __half* Bq = (__half*)smem;                     // [64][136] b-slice (m x kk)
        __half* Pq = (__half*)(smem + 64 * 136 * 2);    // [64][136] Pq[n][kk] = pB[kb*128+kk][nb*64+n]
        const uint32_t bq_base = sbase;
        const uint32_t pq_base = sbase + 64 * 136 * 2;

        // resident operator slice (transposed load, fp16 1-term)
        for (int i = 0; i < 32; i++) {
            const int e = tid + i * 256;
            const int n = e & 63, kk = e >> 6;
            Pq[n * 136 + kk] = __float2half_rn(pB[(size_t)(kb * 128 + kk) * CN + nb * 64 + n]);
        }
        grid_sync();

        const int wm2 = w & 1, wn4 = w >> 1;  // 2 x 4 warp grid over 64x64 tile
        const int arow = wm2 * 32 + (lane & 15);
        const int brow = wn4 * 16 + (lane & 7) + ((lane >> 4) & 1) * 8;
        for (int k = 1; k < NBLK; k++) {
            const float* bsrc = bd + (size_t)(k - 1) * CB * CN;
            for (int i = 0; i < 32; i++) {
                const int e = tid + i * 256;
                const int m = e >> 7, kk = e & 127;
                Bq[m * 136 + kk] = __float2half_rn(bsrc[(size_t)m * CN + kb * 128 + kk]);
            }
            __syncthreads();

            float acc2[2][2][4];
#pragma unroll
            for (int i = 0; i < 2; i++)
#pragma unroll
                for (int j2 = 0; j2 < 2; j2++)
#pragma unroll
                    for (int r = 0; r < 4; r++) acc2[i][j2][r] = 0.f;
#pragma unroll
            for (int kk16 = 0; kk16 < 8; kk16++) {
                const int akc = kk16 * 16 + (lane >> 4) * 8;
                const int bkc = kk16 * 16 + ((lane >> 3) & 1) * 8;
                uint32_t af[2][4], bf[4];
#pragma unroll
                for (int mi = 0; mi < 2; mi++)
                    ldsm4(af[mi][0], af[mi][1], af[mi][2], af[mi][3],
                          bq_base + (uint32_t)((arow + mi * 16) * 272 + akc * 2));
                ldsm4(bf[0], bf[1], bf[2], bf[3],
                      pq_base + (uint32_t)(brow * 272 + bkc * 2));
#pragma unroll
                for (int mi = 0; mi < 2; mi++)
#pragma unroll
                    for (int sub = 0; sub < 2; sub++)
                        mma16816(acc2[mi][sub], af[mi], bf[sub * 2], bf[sub * 2 + 1]);
            }
            float* dst = part + (size_t)kb * CB * CN;
#pragma unroll
            for (int mi = 0; mi < 2; mi++) {
                const int r0 = wm2 * 32 + mi * 16 + (lane >> 2);
#pragma unroll
                for (int sub = 0; sub < 2; sub++) {
                    const int c = nb * 64 + wn4 * 16 + sub * 8 + (lane & 3) * 2;
                    *(float2*)&dst[(size_t)r0 * CN + c] =
                        make_float2(acc2[mi][sub][0], acc2[mi][sub][1]);
                    *(float2*)&dst[(size_t)(r0 + 8) * CN + c] =
                        make_float2(acc2[mi][sub][2], acc2[mi][sub][3]);
                }
            }
            grid_sync();
            // reduce: b_k = e_k + sum_s part[s]
            {
                const size_t e = (size_t)bid * 512 + tid * 2;
                const int m = (int)(e >> 10), n = (int)(e & 1023);
                float2 v = *(const float2*)&s1[((size_t)(m * NBLK + k)) * CN + n];
#pragma unroll
                for (int s = 0; s < 8; s++) {
                    float2 p = *(const float2*)&part[(size_t)s * CB * CN + e];
                    v.x += p.x; v.y += p.y;
                }
                *(float2*)&bd[(size_t)k * CB * CN + e] = v;
            }
            grid_sync();
        }
    }

    // ===== init3: p1h <- fp16(seed) =====
    {
        const size_t base = (size_t)bid * 16384;
#pragma unroll
        for (int i = 0; i < 16; i++) {
            const size_t e = base + (size_t)(tid + i * 256) * 4;
            const int r = (int)(e >> 10), n = (int)(e & 1023);
            const int bb = r >> 5, blk = r & 31;
            float4 v = make_float4(0.f, 0.f, 0.f, 0.f);
            if (blk) v = *(const float4*)&bd[((size_t)(blk - 1) * CB + bb) * CN + n];
            *(__half2*)&p1h[e]     = __floats2half2_rn(v.x, v.y);
            *(__half2*)&p1h[e + 2] = __floats2half2_rn(v.z, v.w);
        }
    }
    grid_sync();

    // ===== pass3: j = 0..15 (1-term) =====
    for (int j = 0; j < S_; j++) {
        const bool in1 = ((j & 1) == 0);
        const __half* ih = in1 ? p1h : p2h;
        __half* oh = in1 ? p2h : p1h;
        float acc[4][4][4];
        gemm_core1(sbase, tid, wm, wn, lane, ih, wah, row0, col0, acc);
        step_epi(acc, row0, col0, wm, wn, lane, xp, j, nullptr, oh, ah);
        if (j < S_ - 1) grid_sync();
    }
}

// =====================================================================
// Standalone big GEMM (phase A / Y): C = A@W^T + bias, 1-term
// =====================================================================
__global__ __launch_bounds__(256, 2) void mma_gemm_bias(
    const __half* __restrict__ Ah, const __half* __restrict__ Bh,
    const float* __restrict__ bias, float* __restrict__ out)
{
    extern __shared__ char smem[];
    const uint32_t sbase = smem_u32(smem);
    const int tid = threadIdx.x, lane = tid & 31, w = tid >> 5;
    const int wm = w & 1, wn = w >> 1;
    const int row0 = blockIdx.y * 128, col0 = blockIdx.x * 128;
    float acc[4][4][4];
    gemm_core1(sbase, tid, wm, wn, lane, Ah, Bh, row0, col0, acc);
#pragma unroll
    for (int mi = 0; mi < 4; mi++) {
        const int rbase = row0 + wm * 64 + mi * 16 + (lane >> 2);
#pragma unroll
        for (int half = 0; half < 2; half++) {
            const int m = rbase + half * 8;
#pragma unroll
            for (int ni = 0; ni < 4; ni++) {
                const int c = col0 + wn * 32 + ni * 8 + (lane & 3) * 2;
                float v0 = acc[mi][ni][half * 2 + 0] + bias[c];
                float v1 = acc[mi][ni][half * 2 + 1] + bias[c + 1];
                *(float2*)&out[(size_t)m * CN + c] = make_float2(v0, v1);
            }
        }
    }
}

// ---------------- prep kernels ----------------
__global__ __launch_bounds__(256) void hsplit_k(
    const float* __restrict__ src, __half* __restrict__ hi)
{
    const size_t e = ((size_t)blockIdx.x * 256 + threadIdx.x) * 4;
    float4 v = *(const float4*)&src[e];
    *(__half2*)&hi[e]     = __floats2half2_rn(v.x, v.y);
    *(__half2*)&hi[e + 2] = __floats2half2_rn(v.z, v.w);
}

__global__ __launch_bounds__(256) void wsplit_k(
    const float* __restrict__ src, __half* __restrict__ hi, __half* __restrict__ lo)
{
    const size_t e = ((size_t)blockIdx.x * 256 + threadIdx.x) * 4;
    float4 v = *(const float4*)&src[e];
    __half h0 = __float2half_rn(v.x), h1 = __float2half_rn(v.y);
    __half h2 = __float2half_rn(v.z), h3 = __float2half_rn(v.w);
    hi[e] = h0; hi[e + 1] = h1; hi[e + 2] = h2; hi[e + 3] = h3;
    lo[e]     = __float2half_rn(v.x - __half2float(h0));
    lo[e + 1] = __float2half_rn(v.y - __half2float(h1));
    lo[e + 2] = __float2half_rn(v.z - __half2float(h2));
    lo[e + 3] = __float2half_rn(v.w - __half2float(h3));
}

__global__ __launch_bounds__(256) void tsplit_k(
    const float* __restrict__ src, __half* __restrict__ hi)
{
    __shared__ float ts[32][33];
    const int x = threadIdx.x & 31, y8 = threadIdx.x >> 5;
    const int tr = blockIdx.y, tc = blockIdx.x;
#pragma unroll
    for (int p = 0; p < 4; p++) {
        const int y = y8 + p * 8;
        ts[y][x] = src[(size_t)(tr * 32 + y) * CN + tc * 32 + x];
    }
    __syncthreads();
#pragma unroll
    for (int p = 0; p < 4; p++) {
        const int y = y8 + p * 8;
        hi[(size_t)(tc * 32 + y) * CN + tr * 32 + x] = __float2half_rn(ts[x][y]);
    }
}

// =====================================================================
// host
// =====================================================================
extern "C" void kernel_launch(void* const* d_in, const int* in_sizes, int n_in,
                              void* d_out, int out_size)
{
    const float* X   = (const float*)d_in[0];
    const float* Wax = (const float*)d_in[1];
    const float* Waa = (const float*)d_in[2];
    const float* ba  = (const float*)d_in[3];
    const float* Wy  = (const float*)d_in[4];
    const float* by  = (const float*)d_in[5];
    float* Y = (float*)d_out;

    void *xpv, *xhv, *ahv, *s1v, *p1hv, *p2hv, *q2hv, *q2lv;
    void *wxhv, *wahv, *walv, *wyhv, *wthv;
    void *bdv, *pAv, *pBv, *partv;
    cudaGetSymbolAddress(&xpv, g_xp);   cudaGetSymbolAddress(&xhv, g_xh);
    cudaGetSymbolAddress(&ahv, g_ah);   cudaGetSymbolAddress(&s1v, g_s1);
    cudaGetSymbolAddress(&p1hv, g_p1h); cudaGetSymbolAddress(&p2hv, g_p2h);
    cudaGetSymbolAddress(&q2hv, g_q2h); cudaGetSymbolAddress(&q2lv, g_q2l);
    cudaGetSymbolAddress(&wxhv, g_wxh);
    cudaGetSymbolAddress(&wahv, g_wah); cudaGetSymbolAddress(&walv, g_wal);
    cudaGetSymbolAddress(&wyhv, g_wyh); cudaGetSymbolAddress(&wthv, g_wth);
    cudaGetSymbolAddress(&bdv, g_bd);   cudaGetSymbolAddress(&pAv, g_pA);
    cudaGetSymbolAddress(&pBv, g_pB);   cudaGetSymbolAddress(&partv, g_part);

    float* xp = (float*)xpv; float* s1 = (float*)s1v;
    float* bd = (float*)bdv; float* pA = (float*)pAv; float* pB = (float*)pBv;
    float* part = (float*)partv;
    __half* xh  = (__half*)xhv;  __half* ah  = (__half*)ahv;
    __half* p1h = (__half*)p1hv; __half* p2h = (__half*)p2hv;
    __half* q2h = (__half*)q2hv; __half* q2l = (__half*)q2lv;
    __half* wxh = (__half*)wxhv;
    __half* wah = (__half*)wahv; __half* wal = (__half*)walv;
    __half* wyh = (__half*)wyhv; __half* wth = (__half*)wthv;

    cudaFuncSetAttribute(mma_gemm_bias, cudaFuncAttributeMaxDynamicSharedMemorySize, GEMM_SMEM);
    cudaFuncSetAttribute(mega_k,        cudaFuncAttributeMaxDynamicSharedMemorySize, MEGA_SMEM);

    // ---- prep ----
    hsplit_k<<<(MROWS * CN) / 1024, 256>>>(X, xh);
    hsplit_k<<<(CN * CN) / 1024, 256>>>(Wax, wxh);
    hsplit_k<<<(CN * CN) / 1024, 256>>>(Wy, wyh);
    wsplit_k<<<(CN * CN) / 1024, 256>>>(Waa, wah, wal);
    tsplit_k<<<dim3(32, 32), 256>>>(Waa, wth);

    // ---- Phase A: Xp = X @ Wax^T + ba ----
    mma_gemm_bias<<<dim3(CN / 128, MROWS / 128), 256, GEMM_SMEM>>>(
        xh, wxh, ba, xp);

    // ---- persistent middle ----
    mega_k<<<NCTA, 256, MEGA_SMEM>>>(
        xp, p1h, p2h, q2h, q2l, wah, wal, wth,
        s1, bd, pA, pB, part, ah);

    // ---- Phase Y: Y = A @ Wy^T + by ----
    mma_gemm_bias<<<dim3(CN / 128, MROWS / 128), 256, GEMM_SMEM>>>(
        ah, wyh, by, Y);
}